// round 15
// baseline (speedup 1.0000x reference)
#include <cuda_runtime.h>
#include <cuda_fp16.h>
#include <math.h>
#include <stdint.h>

#define C_CH 256
#define POOL 7
#define FEAT (POOL*POOL*C_CH)      /* 12544 */
#define R_MAX 1024
#define DCLS_MAX 80
#define M_MAX (R_MAX*DCLS_MAX)
#define NIMG_MAX 4
#define NHEAD_MAX 408
#define LOG_MAX_CONST 4.1351665567423556f

/* ------------------ scratch ---------------------------------------------------------- */
__device__ __half g_x0h[(size_t)R_MAX*FEAT];
__device__ __half g_x0l[(size_t)R_MAX*FEAT];
__device__ __half g_W0th[(size_t)1024*FEAT];
__device__ __half g_W0tl[(size_t)1024*FEAT];
__device__ __half g_W1th[(size_t)1024*1024];
__device__ __half g_W1tl[(size_t)1024*1024];
__device__ __half g_Whth[(size_t)NHEAD_MAX*1024];
__device__ __half g_Whtl[(size_t)NHEAD_MAX*1024];
__device__ __half g_x1h[(size_t)R_MAX*1024];
__device__ __half g_x1l[(size_t)R_MAX*1024];
__device__ __half g_x2h[(size_t)R_MAX*1024];
__device__ __half g_x2l[(size_t)R_MAX*1024];
__device__ float  g_part[(size_t)8*R_MAX*1024];
__device__ float  g_headout[(size_t)R_MAX*NHEAD_MAX];
__device__ float  g_bhead[NHEAD_MAX];
__device__ float  g_cscore[M_MAX];
__device__ float4 g_cbox[M_MAX];
__device__ float  g_score_c[(size_t)NIMG_MAX*M_MAX];
__device__ float4 g_box_c[(size_t)NIMG_MAX*M_MAX];
__device__ float  g_area_c[(size_t)NIMG_MAX*M_MAX];
__device__ int    g_cls_c[(size_t)NIMG_MAX*M_MAX];
__device__ int    g_cnt[NIMG_MAX];
__device__ int    g_ccnt[NIMG_MAX*32];

/* ------------------ helpers --------------------------------------------------------- */
__device__ __forceinline__ uint32_t smem_u32(const void* p) {
    uint32_t a;
    asm("{ .reg .u64 t; cvta.to.shared.u64 t, %1; cvt.u32.u64 %0, t; }" : "=r"(a) : "l"(p));
    return a;
}
__device__ __forceinline__ void split_h(float v, __half& hi, __half& lo)
{
    hi = __float2half_rn(v);
    lo = __float2half_rn(v - __half2float(hi));
}

#define LDSM4(r0,r1,r2,r3, addr) \
    asm volatile("ldmatrix.sync.aligned.m8n8.x4.shared.b16 {%0,%1,%2,%3}, [%4];" \
        : "=r"(r0),"=r"(r1),"=r"(r2),"=r"(r3) : "r"(addr))

#define MMA16816(d, a, b) \
    asm volatile("mma.sync.aligned.m16n8k16.row.col.f32.f16.f16.f32 " \
        "{%0,%1,%2,%3}, {%4,%5,%6,%7}, {%8,%9}, {%0,%1,%2,%3};" \
        : "+f"((d)[0]), "+f"((d)[1]), "+f"((d)[2]), "+f"((d)[3]) \
        : "r"((a)[0]), "r"((a)[1]), "r"((a)[2]), "r"((a)[3]), "r"((b)[0]), "r"((b)[1]))

#define CPASYNC16(dst, src, sz) \
    asm volatile("cp.async.ca.shared.global [%0], [%1], 16, %2;" \
        :: "r"(dst), "l"(src), "r"(sz))

/* ------------------ ROI align (proposal-offset variant) ----------------------------- */
__global__ void roi_align_kernel(const float* __restrict__ prop,
                                 const int*   __restrict__ imidx,
                                 const float* __restrict__ f0, const float* __restrict__ f1,
                                 const float* __restrict__ f2, const float* __restrict__ f3,
                                 int H0, int H1, int H2, int H3, int rOff)
{
    int r = rOff + blockIdx.x;
    __shared__ int   s_lvl, s_img, s_H;
    __shared__ int   s_y0[49], s_y1[49], s_x0[49], s_x1[49];
    __shared__ float s_wx[49], s_wy[49];

    if (threadIdx.x == 0) {
        float x1 = prop[r*4+0], y1 = prop[r*4+1], x2 = prop[r*4+2], y2 = prop[r*4+3];
        float pw = x2 - x1, ph = y2 - y1;
        float l = floorf(4.0f + log2f(sqrtf(pw*ph) / 224.0f + 1e-6f));
        l = fminf(fmaxf(l, 2.0f), 5.0f);
        int lvl = (int)l - 2;
        s_lvl = lvl;
        s_img = imidx[r];
        s_H   = (lvl==0 ? H0 : lvl==1 ? H1 : lvl==2 ? H2 : H3);
    }
    __syncthreads();
    int lvl = s_lvl, H = s_H;

    if (threadIdx.x < 49) {
        int py = threadIdx.x / 7, px = threadIdx.x % 7;
        float s  = 1.0f / (float)(4 << lvl);
        float x1 = prop[r*4+0]*s, y1 = prop[r*4+1]*s;
        float x2 = prop[r*4+2]*s, y2 = prop[r*4+3]*s;
        float gx = (px + 0.5f) / (float)POOL;
        float gy = (py + 0.5f) / (float)POOL;
        float xx = x1 + gx*(x2 - x1) - 0.5f;
        float yy = y1 + gy*(y2 - y1) - 0.5f;
        float x0f = floorf(xx), y0f = floorf(yy);
        s_wx[threadIdx.x] = xx - x0f;
        s_wy[threadIdx.x] = yy - y0f;
        int xi = (int)x0f, yi = (int)y0f;
        s_x0[threadIdx.x] = min(max(xi,     0), H-1);
        s_x1[threadIdx.x] = min(max(xi + 1, 0), H-1);
        s_y0[threadIdx.x] = min(max(yi,     0), H-1);
        s_y1[threadIdx.x] = min(max(yi + 1, 0), H-1);
    }
    __syncthreads();

    const float* fm = (lvl==0 ? f0 : lvl==1 ? f1 : lvl==2 ? f2 : f3);
    size_t imgBase = (size_t)s_img * H * H * C_CH;
    int c4 = (threadIdx.x & 63) << 2;
    int bq = threadIdx.x >> 6;
    size_t outBase = (size_t)r * FEAT;

    for (int b = bq; b < 49; b += 4) {
        float wx = s_wx[b], wy = s_wy[b];
        size_t row0 = imgBase + (size_t)s_y0[b] * H * C_CH;
        size_t row1 = imgBase + (size_t)s_y1[b] * H * C_CH;
        size_t cx0  = (size_t)s_x0[b] * C_CH + c4;
        size_t cx1  = (size_t)s_x1[b] * C_CH + c4;
        float4 v00 = *(const float4*)&fm[row0 + cx0];
        float4 v01 = *(const float4*)&fm[row0 + cx1];
        float4 v10 = *(const float4*)&fm[row1 + cx0];
        float4 v11 = *(const float4*)&fm[row1 + cx1];
        float w00 = (1.f-wx)*(1.f-wy), w01 = wx*(1.f-wy);
        float w10 = (1.f-wx)*wy,       w11 = wx*wy;
        float o0 = v00.x*w00 + v01.x*w01 + v10.x*w10 + v11.x*w11;
        float o1 = v00.y*w00 + v01.y*w01 + v10.y*w10 + v11.y*w11;
        float o2 = v00.z*w00 + v01.z*w01 + v10.z*w10 + v11.z*w11;
        float o3 = v00.w*w00 + v01.w*w01 + v10.w*w10 + v11.w*w11;
        __half h0,l0,h1,l1,h2,l2,h3,l3;
        split_h(o0,h0,l0); split_h(o1,h1,l1); split_h(o2,h2,l2); split_h(o3,h3,l3);
        uint2 ph, pl;
        ph.x = (uint32_t)__half_as_ushort(h0) | ((uint32_t)__half_as_ushort(h1) << 16);
        ph.y = (uint32_t)__half_as_ushort(h2) | ((uint32_t)__half_as_ushort(h3) << 16);
        pl.x = (uint32_t)__half_as_ushort(l0) | ((uint32_t)__half_as_ushort(l1) << 16);
        pl.y = (uint32_t)__half_as_ushort(l2) | ((uint32_t)__half_as_ushort(l3) << 16);
        *(uint2*)&g_x0h[outBase + b*C_CH + c4] = ph;
        *(uint2*)&g_x0l[outBase + b*C_CH + c4] = pl;
    }
}

/* ------------------ transpose + fp16 split: W0 only --------------------------------- */
__global__ void tsplit_w0_kernel(const float* __restrict__ W0, int N0)
{
    __shared__ float tile[32][33];
    int k0 = blockIdx.y * 32, n0 = blockIdx.x * 32;
    int tx = threadIdx.x, ty = threadIdx.y;
    #pragma unroll
    for (int j = 0; j < 4; j++) {
        int k = k0 + ty + j*8, n = n0 + tx;
        tile[ty + j*8][tx] = (k < FEAT && n < N0) ? W0[(size_t)k * N0 + n] : 0.f;
    }
    __syncthreads();
    #pragma unroll
    for (int j = 0; j < 4; j++) {
        int n = n0 + ty + j*8, k = k0 + tx;
        if (n < N0 && k < FEAT) {
            __half h, l; split_h(tile[tx][ty + j*8], h, l);
            size_t o = (size_t)n * FEAT + k;
            g_W0th[o] = h;
            g_W0tl[o] = l;
        }
    }
}

/* ------------------ transpose + fp16 split: W1 / Wc / Wr ---------------------------- */
__global__ void tsplit_rest_kernel(const float* __restrict__ W1,
                                   const float* __restrict__ Wc,
                                   const float* __restrict__ Wr,
                                   int N1, int NC, int NR)
{
    __shared__ float tile[32][33];
    int by = blockIdx.y;
    const float* in; __half *outH, *outL;
    int K, N, roff, Kout, kseg;
    if (by < 32)      { in = W1; K = N1; N = N1; roff = 0;  Kout = N1; kseg = by;
                        outH = g_W1th; outL = g_W1tl; }
    else if (by < 64) { in = Wc; K = N1; N = NC; roff = 0;  Kout = N1; kseg = by - 32;
                        outH = g_Whth; outL = g_Whtl; }
    else              { in = Wr; K = N1; N = NR; roff = NC; Kout = N1; kseg = by - 64;
                        outH = g_Whth; outL = g_Whtl; }

    int k0 = kseg * 32, n0 = blockIdx.x * 32;
    if (n0 >= N || k0 >= K) return;
    int tx = threadIdx.x, ty = threadIdx.y;
    #pragma unroll
    for (int j = 0; j < 4; j++) {
        int k = k0 + ty + j*8, n = n0 + tx;
        tile[ty + j*8][tx] = (k < K && n < N) ? in[(size_t)k * N + n] : 0.f;
    }
    __syncthreads();
    #pragma unroll
    for (int j = 0; j < 4; j++) {
        int n = n0 + ty + j*8, k = k0 + tx;
        if (n < N && k < Kout) {
            __half h, l; split_h(tile[tx][ty + j*8], h, l);
            size_t o = (size_t)(roff + n) * Kout + k;
            outH[o] = h;
            outL[o] = l;
        }
    }
}

__global__ void pack_bias_kernel(const float* __restrict__ bc, const float* __restrict__ br,
                                 int NC, int NR)
{
    int t = threadIdx.x;
    if (t < NC + NR)
        g_bhead[t] = (t < NC) ? bc[t] : br[t - NC];
}

/* ------------------ fp16x2 GEMM (3-stage proven config, +row offset) ---------------- */
#define B_OFF 16384
#define GSTG  24576
#define GT_STAGES 3
#define GT_DSMEM (GT_STAGES*GSTG)   /* 73728 */

__global__ __launch_bounds__(256, 2) void gemm_h2(
    const __half* __restrict__ Ah, const __half* __restrict__ Al,
    const __half* __restrict__ Bh, const __half* __restrict__ Bl,
    float* __restrict__ Cp, int M, int N, int K, int Ksl, int mOff)
{
    extern __shared__ __align__(16) char sm[];
    uint32_t smb = smem_u32(sm);

    int tid = threadIdx.x, lane = tid & 31, warp = tid >> 5;
    int mBase = mOff + blockIdx.y * 128, nBase = blockIdx.x * 64;
    int kOff = blockIdx.z * Ksl;
    int wm = (warp & 3) * 32, wn = (warp >> 2) * 32;

    float acc[2][4][4];
    #pragma unroll
    for (int i = 0; i < 2; i++)
        #pragma unroll
        for (int j = 0; j < 4; j++)
            #pragma unroll
            for (int q = 0; q < 4; q++) acc[i][j][q] = 0.f;

    int Keff = K - kOff; if (Keff > Ksl) Keff = Ksl;
    int tiles = Keff >> 5;

    int arow0 = tid >> 2, akc0 = tid & 3;
    auto loadTile = [&](int t) {
        if (t < tiles) {
            int kt = kOff + (t << 5);
            uint32_t base = smb + (uint32_t)(t % GT_STAGES) * GSTG;
            #pragma unroll
            for (int i = 0; i < 2; i++) {
                int row = arow0 + i*64;
                size_t gi = (size_t)(mBase + row) * K + kt + akc0*8;
                uint32_t rb = base + (uint32_t)row*128u;
                uint32_t sw = (uint32_t)(row & 7);
                int sz = (mBase + row < M) ? 16 : 0;
                CPASYNC16(rb + ((((uint32_t)akc0*2u    ) ^ sw) << 4), Ah + gi, sz);
                CPASYNC16(rb + ((((uint32_t)akc0*2u + 1u) ^ sw) << 4), Al + gi, sz);
            }
            {
                int row = (tid >> 2) & 63;
                int kc  = akc0;
                size_t gi = (size_t)(nBase + row) * K + kt + kc*8;
                uint32_t rb = base + B_OFF + (uint32_t)row*128u;
                uint32_t sw = (uint32_t)(row & 7);
                int sz = (nBase + row < N) ? 16 : 0;
                CPASYNC16(rb + ((((uint32_t)kc*2u    ) ^ sw) << 4), Bh + gi, sz);
                CPASYNC16(rb + ((((uint32_t)kc*2u + 1u) ^ sw) << 4), Bl + gi, sz);
            }
        }
        asm volatile("cp.async.commit_group;");
    };

    loadTile(0); loadTile(1);

    int lm = lane >> 3, lr = lane & 7;
    uint32_t aSw = (uint32_t)lr;
    uint32_t akcb = (uint32_t)(lm >> 1);
    uint32_t bkcb = (uint32_t)(lm & 1);
    uint32_t aOffC[2][2], bOffC[2][2];
    #pragma unroll
    for (int ks = 0; ks < 2; ks++) {
        uint32_t cA = (akcb + (uint32_t)ks*2u) << 1;
        uint32_t cB = (bkcb + (uint32_t)ks*2u) << 1;
        aOffC[ks][0] = ((cA     ) ^ aSw) << 4;
        aOffC[ks][1] = ((cA | 1u) ^ aSw) << 4;
        bOffC[ks][0] = ((cB     ) ^ aSw) << 4;
        bOffC[ks][1] = ((cB | 1u) ^ aSw) << 4;
    }
    uint32_t aRow[2], bRow[2];
    #pragma unroll
    for (int mi = 0; mi < 2; mi++)
        aRow[mi] = (uint32_t)(wm + mi*16 + (lm&1)*8 + lr) * 128u;
    #pragma unroll
    for (int g = 0; g < 2; g++)
        bRow[g] = (uint32_t)B_OFF + (uint32_t)(wn + g*16 + (lm>>1)*8 + lr) * 128u;

    for (int t = 0; t < tiles; t++) {
        asm volatile("cp.async.wait_group 1;");
        __syncthreads();
        loadTile(t + 2);
        uint32_t base = smb + (uint32_t)(t % GT_STAGES) * GSTG;
        uint32_t a0 = base + aRow[0], a1 = base + aRow[1];
        uint32_t b0 = base + bRow[0], b1 = base + bRow[1];

        uint32_t ah[2][2][4], al[2][2][4];
        uint32_t bh[2][4][2], bl[2][4][2];
        #pragma unroll
        for (int ks = 0; ks < 2; ks++) {
            LDSM4(ah[ks][0][0], ah[ks][0][1], ah[ks][0][2], ah[ks][0][3], a0 + aOffC[ks][0]);
            LDSM4(al[ks][0][0], al[ks][0][1], al[ks][0][2], al[ks][0][3], a0 + aOffC[ks][1]);
            LDSM4(ah[ks][1][0], ah[ks][1][1], ah[ks][1][2], ah[ks][1][3], a1 + aOffC[ks][0]);
            LDSM4(al[ks][1][0], al[ks][1][1], al[ks][1][2], al[ks][1][3], a1 + aOffC[ks][1]);
            uint32_t r0, r1, r2, r3;
            LDSM4(r0, r1, r2, r3, b0 + bOffC[ks][0]);
            bh[ks][0][0]=r0; bh[ks][0][1]=r1; bh[ks][1][0]=r2; bh[ks][1][1]=r3;
            LDSM4(r0, r1, r2, r3, b0 + bOffC[ks][1]);
            bl[ks][0][0]=r0; bl[ks][0][1]=r1; bl[ks][1][0]=r2; bl[ks][1][1]=r3;
            LDSM4(r0, r1, r2, r3, b1 + bOffC[ks][0]);
            bh[ks][2][0]=r0; bh[ks][2][1]=r1; bh[ks][3][0]=r2; bh[ks][3][1]=r3;
            LDSM4(r0, r1, r2, r3, b1 + bOffC[ks][1]);
            bl[ks][2][0]=r0; bl[ks][2][1]=r1; bl[ks][3][0]=r2; bl[ks][3][1]=r3;
        }

        #pragma unroll
        for (int ks = 0; ks < 2; ks++) {
            #pragma unroll
            for (int mi = 0; mi < 2; mi++)
                #pragma unroll
                for (int nj = 0; nj < 4; nj++)
                    MMA16816(acc[mi][nj], ah[ks][mi], bh[ks][nj]);
            #pragma unroll
            for (int mi = 0; mi < 2; mi++)
                #pragma unroll
                for (int nj = 0; nj < 4; nj++)
                    MMA16816(acc[mi][nj], ah[ks][mi], bl[ks][nj]);
            #pragma unroll
            for (int mi = 0; mi < 2; mi++)
                #pragma unroll
                for (int nj = 0; nj < 4; nj++)
                    MMA16816(acc[mi][nj], al[ks][mi], bh[ks][nj]);
        }
    }

    /* epilogue: raw fp32 partial */
    float* out = Cp + (size_t)blockIdx.z * M * N;
    #pragma unroll
    for (int mi = 0; mi < 2; mi++) {
        #pragma unroll
        for (int nj = 0; nj < 4; nj++) {
            #pragma unroll
            for (int q = 0; q < 4; q++) {
                int row = mBase + wm + mi*16 + (lane >> 2) + (q >> 1)*8;
                int col = nBase + wn + nj*8 + ((lane & 3) << 1) + (q & 1);
                if (row < M && col < N)
                    out[(size_t)row * N + col] = acc[mi][nj][q];
            }
        }
    }
}

/* ------------------ split-K reduce (float4 fast path when N%4==0) ------------------- */
__global__ void reduce_kernel(const float* __restrict__ part, const float* __restrict__ bias,
                              int M, int N, int nsl, int relu,
                              float* __restrict__ outF,
                              __half* __restrict__ outH, __half* __restrict__ outL)
{
    size_t total = (size_t)M * N;
    if ((N & 3) == 0) {
        size_t base = ((size_t)blockIdx.x * blockDim.x + threadIdx.x) * 4;
        if (base >= total) return;
        int col = (int)(base % (size_t)N);
        float4 v = *(const float4*)&bias[col];
        for (int s = 0; s < nsl; s++) {
            float4 p = *(const float4*)&part[(size_t)s * total + base];
            v.x += p.x; v.y += p.y; v.z += p.z; v.w += p.w;
        }
        if (relu) {
            v.x = fmaxf(v.x, 0.f); v.y = fmaxf(v.y, 0.f);
            v.z = fmaxf(v.z, 0.f); v.w = fmaxf(v.w, 0.f);
            __half h0,l0,h1,l1,h2,l2,h3,l3;
            split_h(v.x,h0,l0); split_h(v.y,h1,l1); split_h(v.z,h2,l2); split_h(v.w,h3,l3);
            uint2 ph, pl;
            ph.x = (uint32_t)__half_as_ushort(h0) | ((uint32_t)__half_as_ushort(h1) << 16);
            ph.y = (uint32_t)__half_as_ushort(h2) | ((uint32_t)__half_as_ushort(h3) << 16);
            pl.x = (uint32_t)__half_as_ushort(l0) | ((uint32_t)__half_as_ushort(l1) << 16);
            pl.y = (uint32_t)__half_as_ushort(l2) | ((uint32_t)__half_as_ushort(l3) << 16);
            *(uint2*)&outH[base] = ph;
            *(uint2*)&outL[base] = pl;
        } else {
            *(float4*)&outF[base] = v;
        }
    } else {
        size_t idx = (size_t)blockIdx.x * blockDim.x + threadIdx.x;
        if (idx >= total) return;
        int col = (int)(idx % (size_t)N);
        float v = bias[col];
        for (int s = 0; s < nsl; s++) v += part[(size_t)s * total + idx];
        if (relu) {
            v = fmaxf(v, 0.f);
            __half h, l; split_h(v, h, l);
            outH[idx] = h;
            outL[idx] = l;
        } else {
            outF[idx] = v;
        }
    }
}

/* ------------------ softmax + box decode -------------------------------------------- */
__global__ void decode_kernel(const float* __restrict__ prop,
                              const int*   __restrict__ imidx,
                              const float* __restrict__ imsizes,
                              const float* __restrict__ sthr_p,
                              const float* __restrict__ minsz_p,
                              int NC, int NT)
{
    int r = blockIdx.x;
    int t = threadIdx.x;
    __shared__ float sl[128];
    __shared__ float smax, ssum;

    const float* head = &g_headout[(size_t)r * NT];

    if (t < NC) sl[t] = head[t];
    __syncthreads();
    if (t == 0) { float m = sl[0]; for (int i = 1; i < NC; i++) m = fmaxf(m, sl[i]); smax = m; }
    __syncthreads();
    if (t < NC) sl[t] = expf(sl[t] - smax);
    __syncthreads();
    if (t == 0) { float s = 0.f; for (int i = 0; i < NC; i++) s += sl[i]; ssum = s; }
    __syncthreads();

    int D = NC - 1;
    if (t < D) {
        float score = sl[t+1] / ssum;
        float px1 = prop[r*4+0], py1 = prop[r*4+1];
        float px2 = prop[r*4+2], py2 = prop[r*4+3];
        float pw = px2 - px1, ph = py2 - py1;
        float cx = (px1 + px2)*0.5f, cy = (py1 + py2)*0.5f;
        const float* rg = &head[NC + (t+1)*4];
        float dx = rg[0]*0.1f, dy = rg[1]*0.1f;
        float dw = fminf(rg[2]*0.2f, LOG_MAX_CONST);
        float dh = fminf(rg[3]*0.2f, LOG_MAX_CONST);
        float ncx = dx*pw + cx, ncy = dy*ph + cy;
        float nw  = expf(dw)*pw, nh  = expf(dh)*ph;
        int im = imidx[r];
        float hb = imsizes[im*2+0], wb = imsizes[im*2+1];
        float bx1 = fminf(fmaxf(ncx - nw*0.5f, 0.f), wb);
        float bx2 = fminf(fmaxf(ncx + nw*0.5f, 0.f), wb);
        float by1 = fminf(fmaxf(ncy - nh*0.5f, 0.f), hb);
        float by2 = fminf(fmaxf(ncy + nh*0.5f, 0.f), hb);
        float sthr = *sthr_p, minsz = *minsz_p;
        bool valid = (score > sthr) && (bx2 - bx1 >= minsz) && (by2 - by1 >= minsz);
        int m = r*D + t;
        g_cscore[m] = valid ? score : -1.0f;
        g_cbox[m]   = make_float4(bx1, by1, bx2, by2);
    }
}

/* ------------------ two-phase deterministic compaction ------------------------------ */
#define CCH 4096
__global__ void compact_count_kernel(const int* __restrict__ imidx, int M, int D)
{
    int chunk = blockIdx.x, img = blockIdx.y;
    int tid = threadIdx.x, lane = tid & 31, wid = tid >> 5;
    __shared__ int wsum[8];
    int base = chunk * CCH;
    int cnt = 0;
    #pragma unroll 4
    for (int j = 0; j < 16; j++) {
        int m = base + tid*16 + j;
        if (m < M) {
            float v = g_cscore[m];
            if (v > 0.f && imidx[m / D] == img) cnt++;
        }
    }
    #pragma unroll
    for (int o = 16; o; o >>= 1) cnt += __shfl_xor_sync(0xffffffffu, cnt, o);
    if (lane == 0) wsum[wid] = cnt;
    __syncthreads();
    if (tid == 0) {
        int s = 0;
        for (int w = 0; w < 8; w++) s += wsum[w];
        g_ccnt[img*32 + chunk] = s;
    }
}

__global__ void compact_scatter_kernel(const int* __restrict__ imidx, int M, int D, int nch)
{
    int chunk = blockIdx.x, img = blockIdx.y;
    int tid = threadIdx.x, lane = tid & 31, wid = tid >> 5;
    __shared__ int woff[8];
    __shared__ int sbase;
    if (tid == 0) {
        int s = 0;
        for (int c = 0; c < chunk; c++) s += g_ccnt[img*32 + c];
        sbase = s;
        if (chunk == nch - 1) g_cnt[img] = s + g_ccnt[img*32 + chunk];
    }
    int base = chunk * CCH;
    int cnt = 0; int mi[16]; float sv[16];
    for (int j = 0; j < 16; j++) {
        int m = base + tid*16 + j;
        if (m < M) {
            float v = g_cscore[m];
            if (v > 0.f && imidx[m / D] == img) { sv[cnt] = v; mi[cnt] = m; cnt++; }
        }
    }
    int pre = cnt;
    #pragma unroll
    for (int o = 1; o < 32; o <<= 1) {
        int x = __shfl_up_sync(0xffffffffu, pre, o);
        if (lane >= o) pre += x;
    }
    if (lane == 31) woff[wid] = pre;
    __syncthreads();
    int wbase = 0;
    for (int w = 0; w < wid; w++) wbase += woff[w];
    int p = sbase + wbase + pre - cnt;
    for (int q = 0; q < cnt; q++) {
        int m = mi[q];
        size_t o = (size_t)img*M_MAX + p + q;
        float4 b = g_cbox[m];
        g_score_c[o] = sv[q];
        g_box_c[o]   = b;
        g_area_c[o]  = (b.z - b.x)*(b.w - b.y);
        g_cls_c[o]   = (m % D) + 1;
    }
}

/* ------------------ sequential NMS -------------------------------------------------- */
#define NMS_CAP 32768
#define NMS_T   512
__global__ __launch_bounds__(NMS_T) void nms_kernel(const float* __restrict__ iou_p,
                                                    float* __restrict__ out,
                                                    int n, int imtop)
{
    extern __shared__ float ssc[];
    int img = blockIdx.x, tid = threadIdx.x;
    int lane = tid & 31, warp = tid >> 5;
    int K = g_cnt[img];
    float iouT = *iou_p;
    float*  gsc = &g_score_c[(size_t)img*M_MAX];
    float4* bx  = &g_box_c[(size_t)img*M_MAX];
    float*  ar  = &g_area_c[(size_t)img*M_MAX];
    int*    cl  = &g_cls_c[(size_t)img*M_MAX];

    bool useS = (K <= NMS_CAP);
    float* sc = useS ? ssc : gsc;
    if (useS) for (int k = tid; k < K; k += NMS_T) ssc[k] = gsc[k];

    __shared__ unsigned long long wred[NMS_T/32];
    __shared__ float4 shb; __shared__ float sha; __shared__ int shc, shi; __shared__ float shv;
    __syncthreads();

    float* oB = out + (size_t)img*imtop*4;
    float* oS = out + (size_t)n*imtop*4 + (size_t)img*imtop;
    float* oC = out + (size_t)n*imtop*5 + (size_t)img*imtop;

    int t = 0;
    for (; t < imtop; t++) {
        unsigned long long best = 0ull;
        for (int k = tid; k < K; k += NMS_T) {
            float v = sc[k];
            if (v > 0.f) {
                unsigned long long p =
                    ((unsigned long long)__float_as_uint(v) << 32) |
                    (unsigned)(0x7FFFFFFF - k);
                if (p > best) best = p;
            }
        }
        #pragma unroll
        for (int o = 16; o; o >>= 1) {
            unsigned long long q = __shfl_xor_sync(0xffffffffu, best, o);
            if (q > best) best = q;
        }
        if (lane == 0) wred[warp] = best;
        __syncthreads();
        if (warp == 0) {
            unsigned long long b2 = (lane < NMS_T/32) ? wred[lane] : 0ull;
            #pragma unroll
            for (int o = 8; o; o >>= 1) {
                unsigned long long q = __shfl_xor_sync(0xffffffffu, b2, o);
                if (q > b2) b2 = q;
            }
            if (lane == 0) {
                if (b2) {
                    int wi = 0x7FFFFFFF - (int)(unsigned)(b2 & 0xFFFFFFFFu);
                    shv = __uint_as_float((unsigned)(b2 >> 32));
                    shi = wi; shb = bx[wi]; sha = ar[wi]; shc = cl[wi];
                } else {
                    shv = -1.f;
                }
            }
        }
        __syncthreads();
        float wv = shv;
        if (wv <= 0.f) break;
        int wi = shi; float4 wb = shb; float wa = sha; int wc = shc;
        for (int k = tid; k < K; k += NMS_T) {
            float v = sc[k];
            if (v <= 0.f) continue;
            if (k == wi) { sc[k] = -1.f; continue; }
            if (cl[k] != wc) continue;
            float4 b = bx[k];
            float iw = fmaxf(fminf(wb.z, b.z) - fmaxf(wb.x, b.x), 0.f);
            float ih = fmaxf(fminf(wb.w, b.w) - fmaxf(wb.y, b.y), 0.f);
            float inter = iw * ih;
            float iou = inter / (wa + ar[k] - inter + 1e-6f);
            if (iou > iouT) sc[k] = -1.f;
        }
        if (tid == 0) {
            oB[t*4+0] = wb.x; oB[t*4+1] = wb.y; oB[t*4+2] = wb.z; oB[t*4+3] = wb.w;
            oS[t] = wv;
            oC[t] = (float)wc;
        }
        __syncthreads();
    }
    for (int u = t + tid; u < imtop; u += NMS_T) {
        oB[u*4+0] = 0.f; oB[u*4+1] = 0.f; oB[u*4+2] = 0.f; oB[u*4+3] = 0.f;
        oS[u] = 0.f;
        oC[u] = -1.f;
    }
}

/* ------------------ host launch ---------------------------------------------------- */
extern "C" void kernel_launch(void* const* d_in, const int* in_sizes, int n_in,
                              void* d_out, int out_size)
{
    const float* prop    = (const float*)d_in[0];
    const int*   imidx   = (const int*)  d_in[1];
    const float* f0      = (const float*)d_in[2];
    const float* f1      = (const float*)d_in[3];
    const float* f2      = (const float*)d_in[4];
    const float* f3      = (const float*)d_in[5];
    const float* W0      = (const float*)d_in[6];
    const float* b0      = (const float*)d_in[7];
    const float* W1      = (const float*)d_in[8];
    const float* b1      = (const float*)d_in[9];
    const float* Wc      = (const float*)d_in[10];
    const float* bc      = (const float*)d_in[11];
    const float* Wr      = (const float*)d_in[12];
    const float* br      = (const float*)d_in[13];
    const float* imsizes = (const float*)d_in[14];
    const float* sthr    = (const float*)d_in[15];
    const float* iouthr  = (const float*)d_in[16];
    const float* minsz   = (const float*)d_in[18];

    int R  = in_sizes[0] / 4;
    int n  = in_sizes[14] / 2;
    int imtop = out_size / (6 * n);
    int N0 = in_sizes[7];
    int N1 = in_sizes[9];
    int NC = in_sizes[11];
    int NR = in_sizes[13];
    int NT = NC + NR;
    int D  = NC - 1;
    int M  = R * D;

    int H0 = (int)(sqrt((double)in_sizes[2] / ((double)n * C_CH)) + 0.5);
    int H1 = (int)(sqrt((double)in_sizes[3] / ((double)n * C_CH)) + 0.5);
    int H2 = (int)(sqrt((double)in_sizes[4] / ((double)n * C_CH)) + 0.5);
    int H3 = (int)(sqrt((double)in_sizes[5] / ((double)n * C_CH)) + 0.5);

    __half *px0h, *px0l, *pW0h, *pW0l, *pW1h, *pW1l, *pWhh, *pWhl;
    __half *px1h, *px1l, *px2h, *px2l;
    float *phead, *pbh, *ppart;
    cudaGetSymbolAddress((void**)&px0h, g_x0h);  cudaGetSymbolAddress((void**)&px0l, g_x0l);
    cudaGetSymbolAddress((void**)&pW0h, g_W0th); cudaGetSymbolAddress((void**)&pW0l, g_W0tl);
    cudaGetSymbolAddress((void**)&pW1h, g_W1th); cudaGetSymbolAddress((void**)&pW1l, g_W1tl);
    cudaGetSymbolAddress((void**)&pWhh, g_Whth); cudaGetSymbolAddress((void**)&pWhl, g_Whtl);
    cudaGetSymbolAddress((void**)&px1h, g_x1h);  cudaGetSymbolAddress((void**)&px1l, g_x1l);
    cudaGetSymbolAddress((void**)&px2h, g_x2h);  cudaGetSymbolAddress((void**)&px2l, g_x2l);
    cudaGetSymbolAddress((void**)&phead, g_headout);
    cudaGetSymbolAddress((void**)&pbh,   g_bhead);
    cudaGetSymbolAddress((void**)&ppart, g_part);

    cudaFuncSetAttribute(gemm_h2, cudaFuncAttributeMaxDynamicSharedMemorySize, GT_DSMEM);
    cudaFuncSetAttribute(nms_kernel, cudaFuncAttributeMaxDynamicSharedMemorySize, NMS_CAP*4);

    static cudaStream_t s2 = nullptr, s3 = nullptr;
    static cudaEvent_t evFork = nullptr, evW0 = nullptr, evR1 = nullptr,
                       evH1 = nullptr, evJoin = nullptr;
    if (!s2) {
        cudaStreamCreateWithFlags(&s2, cudaStreamNonBlocking);
        cudaStreamCreateWithFlags(&s3, cudaStreamNonBlocking);
        cudaEventCreateWithFlags(&evFork, cudaEventDisableTiming);
        cudaEventCreateWithFlags(&evW0,   cudaEventDisableTiming);
        cudaEventCreateWithFlags(&evR1,   cudaEventDisableTiming);
        cudaEventCreateWithFlags(&evH1,   cudaEventDisableTiming);
        cudaEventCreateWithFlags(&evJoin, cudaEventDisableTiming);
    }

    /* row split: FC1 halves at a 128-multiple boundary */
    int R1 = (R >= 256) ? (((R / 2) + 127) & ~127) : R;
    if (R1 > R) R1 = R;
    int R2 = R - R1;

    cudaEventRecord(evFork, 0);
    cudaStreamWaitEvent(s2, evFork, 0);
    cudaStreamWaitEvent(s3, evFork, 0);

    /* s2: W0 split (gates FC1), then the rest of the weights */
    {
        dim3 b(32, 8);
        tsplit_w0_kernel<<<dim3((N0+31)/32, (FEAT+31)/32), b, 0, s2>>>(W0, N0);
        cudaEventRecord(evW0, s2);
        tsplit_rest_kernel<<<dim3(32, 96), b, 0, s2>>>(W1, Wc, Wr, N1, NC, NR);
        pack_bias_kernel<<<1, 512, 0, s2>>>(bc, br, NC, NR);
        cudaEventRecord(evJoin, s2);
    }

    /* stream 0: roi halves */
    roi_align_kernel<<<R1, 256>>>(prop, imidx, f0, f1, f2, f3, H0, H1, H2, H3, 0);
    cudaEventRecord(evR1, 0);
    if (R2 > 0)
        roi_align_kernel<<<R2, 256>>>(prop, imidx, f0, f1, f2, f3, H0, H1, H2, H3, R1);

    /* s3: FC1 half 1 (rows [0,R1)) overlaps roi half 2 + weight rest */
    cudaStreamWaitEvent(s3, evW0, 0);
    cudaStreamWaitEvent(s3, evR1, 0);
    {
        dim3 g((N0 + 63)/64, R1/128, 7);
        gemm_h2<<<g, 256, GT_DSMEM, s3>>>(px0h, px0l, pW0h, pW0l, ppart, R, N0, FEAT, 1792, 0);
    }
    cudaEventRecord(evH1, s3);

    /* stream 0: FC1 half 2 (rows [R1,R)) */
    cudaStreamWaitEvent(0, evW0, 0);
    if (R2 > 0) {
        dim3 g((N0 + 63)/64, R2/128, 7);
        gemm_h2<<<g, 256, GT_DSMEM>>>(px0h, px0l, pW0h, pW0l, ppart, R, N0, FEAT, 1792, R1);
    }
    cudaStreamWaitEvent(0, evH1, 0);

    int rdT = 256;
    /* FC1 reduce (relu + split) */
    {
        size_t tot = (size_t)R * N0;
        int thr = (int)((N0 & 3) == 0 ? (tot + 3)/4 : tot);
        reduce_kernel<<<(thr + rdT - 1)/rdT, rdT>>>(ppart, b0, R, N0, 7, 1,
                                                    nullptr, px1h, px1l);
    }
    /* FC2 (needs W1 from tsplit_rest) */
    cudaStreamWaitEvent(0, evJoin, 0);
    {
        dim3 g((N1 + 63)/64, (R + 127)/128, 2);
        gemm_h2<<<g, 256, GT_DSMEM>>>(px1h, px1l, pW1h, pW1l, ppart, R, N1, N0, 512, 0);
        size_t tot = (size_t)R * N1;
        int thr = (int)((N1 & 3) == 0 ? (tot + 3)/4 : tot);
        reduce_kernel<<<(thr + rdT - 1)/rdT, rdT>>>(ppart, b1, R, N1, 2, 1,
                                                    nullptr, px2h, px2l);
    }
    /* fused head */
    {
        dim3 g((NT + 63)/64, (R + 127)/128, 5);
        gemm_h2<<<g, 256, GT_DSMEM>>>(px2h, px2l, pWhh, pWhl, ppart, R, NT, N1, 224, 0);
        size_t tot = (size_t)R * NT;
        int thr = (int)((NT & 3) == 0 ? (tot + 3)/4 : tot);
        reduce_kernel<<<(thr + rdT - 1)/rdT, rdT>>>(ppart, pbh, R, NT, 5, 0,
                                                    phead, nullptr, nullptr);
    }
    /* decode, compaction, NMS */
    decode_kernel<<<R, 128>>>(prop, imidx, imsizes, sthr, minsz, NC, NT);
    {
        int nch = (M + CCH - 1) / CCH;
        compact_count_kernel<<<dim3(nch, n), 256>>>(imidx, M, D);
        compact_scatter_kernel<<<dim3(nch, n), 256>>>(imidx, M, D, nch);
    }
    nms_kernel<<<n, NMS_T, NMS_CAP*4>>>(iouthr, (float*)d_out, n, imtop);
}

// round 16
// speedup vs baseline: 1.0202x; 1.0202x over previous
#include <cuda_runtime.h>
#include <cuda_fp16.h>
#include <math.h>
#include <stdint.h>

#define C_CH 256
#define POOL 7
#define FEAT (POOL*POOL*C_CH)      /* 12544 */
#define R_MAX 1024
#define DCLS_MAX 80
#define M_MAX (R_MAX*DCLS_MAX)
#define NIMG_MAX 4
#define NHEAD_MAX 408
#define LOG_MAX_CONST 4.1351665567423556f

/* ------------------ scratch ---------------------------------------------------------- */
__device__ __half g_x0h[(size_t)R_MAX*FEAT];
__device__ __half g_x0l[(size_t)R_MAX*FEAT];
__device__ __half g_W0th[(size_t)1024*FEAT];
__device__ __half g_W0tl[(size_t)1024*FEAT];
__device__ __half g_W1th[(size_t)1024*1024];
__device__ __half g_W1tl[(size_t)1024*1024];
__device__ __half g_Whth[(size_t)NHEAD_MAX*1024];
__device__ __half g_Whtl[(size_t)NHEAD_MAX*1024];
__device__ __half g_x1h[(size_t)R_MAX*1024];
__device__ __half g_x1l[(size_t)R_MAX*1024];
__device__ __half g_x2h[(size_t)R_MAX*1024];
__device__ __half g_x2l[(size_t)R_MAX*1024];
__device__ float  g_part[(size_t)8*R_MAX*1024];
__device__ float  g_headout[(size_t)R_MAX*NHEAD_MAX];
__device__ float  g_bhead[NHEAD_MAX];
__device__ float  g_cscore[M_MAX];
__device__ float4 g_cbox[M_MAX];
__device__ float  g_score_c[(size_t)NIMG_MAX*M_MAX];
__device__ float4 g_box_c[(size_t)NIMG_MAX*M_MAX];
__device__ float  g_area_c[(size_t)NIMG_MAX*M_MAX];
__device__ int    g_cls_c[(size_t)NIMG_MAX*M_MAX];
__device__ int    g_cnt[NIMG_MAX];
__device__ int    g_ccnt[NIMG_MAX*32];

/* ------------------ helpers --------------------------------------------------------- */
__device__ __forceinline__ uint32_t smem_u32(const void* p) {
    uint32_t a;
    asm("{ .reg .u64 t; cvta.to.shared.u64 t, %1; cvt.u32.u64 %0, t; }" : "=r"(a) : "l"(p));
    return a;
}
__device__ __forceinline__ void split_h(float v, __half& hi, __half& lo)
{
    hi = __float2half_rn(v);
    lo = __float2half_rn(v - __half2float(hi));
}

#define LDSM4(r0,r1,r2,r3, addr) \
    asm volatile("ldmatrix.sync.aligned.m8n8.x4.shared.b16 {%0,%1,%2,%3}, [%4];" \
        : "=r"(r0),"=r"(r1),"=r"(r2),"=r"(r3) : "r"(addr))

#define MMA16816(d, a, b) \
    asm volatile("mma.sync.aligned.m16n8k16.row.col.f32.f16.f16.f32 " \
        "{%0,%1,%2,%3}, {%4,%5,%6,%7}, {%8,%9}, {%0,%1,%2,%3};" \
        : "+f"((d)[0]), "+f"((d)[1]), "+f"((d)[2]), "+f"((d)[3]) \
        : "r"((a)[0]), "r"((a)[1]), "r"((a)[2]), "r"((a)[3]), "r"((b)[0]), "r"((b)[1]))

#define CPASYNC16(dst, src, sz) \
    asm volatile("cp.async.ca.shared.global [%0], [%1], 16, %2;" \
        :: "r"(dst), "l"(src), "r"(sz))

/* ------------------ ROI align (round-14 proven) ------------------------------------- */
__global__ void roi_align_kernel(const float* __restrict__ prop,
                                 const int*   __restrict__ imidx,
                                 const float* __restrict__ f0, const float* __restrict__ f1,
                                 const float* __restrict__ f2, const float* __restrict__ f3,
                                 int H0, int H1, int H2, int H3)
{
    int r = blockIdx.x;
    __shared__ int   s_lvl, s_img, s_H;
    __shared__ int   s_y0[49], s_y1[49], s_x0[49], s_x1[49];
    __shared__ float s_wx[49], s_wy[49];

    if (threadIdx.x == 0) {
        float x1 = prop[r*4+0], y1 = prop[r*4+1], x2 = prop[r*4+2], y2 = prop[r*4+3];
        float pw = x2 - x1, ph = y2 - y1;
        float l = floorf(4.0f + log2f(sqrtf(pw*ph) / 224.0f + 1e-6f));
        l = fminf(fmaxf(l, 2.0f), 5.0f);
        int lvl = (int)l - 2;
        s_lvl = lvl;
        s_img = imidx[r];
        s_H   = (lvl==0 ? H0 : lvl==1 ? H1 : lvl==2 ? H2 : H3);
    }
    __syncthreads();
    int lvl = s_lvl, H = s_H;

    if (threadIdx.x < 49) {
        int py = threadIdx.x / 7, px = threadIdx.x % 7;
        float s  = 1.0f / (float)(4 << lvl);
        float x1 = prop[r*4+0]*s, y1 = prop[r*4+1]*s;
        float x2 = prop[r*4+2]*s, y2 = prop[r*4+3]*s;
        float gx = (px + 0.5f) / (float)POOL;
        float gy = (py + 0.5f) / (float)POOL;
        float xx = x1 + gx*(x2 - x1) - 0.5f;
        float yy = y1 + gy*(y2 - y1) - 0.5f;
        float x0f = floorf(xx), y0f = floorf(yy);
        s_wx[threadIdx.x] = xx - x0f;
        s_wy[threadIdx.x] = yy - y0f;
        int xi = (int)x0f, yi = (int)y0f;
        s_x0[threadIdx.x] = min(max(xi,     0), H-1);
        s_x1[threadIdx.x] = min(max(xi + 1, 0), H-1);
        s_y0[threadIdx.x] = min(max(yi,     0), H-1);
        s_y1[threadIdx.x] = min(max(yi + 1, 0), H-1);
    }
    __syncthreads();

    const float* fm = (lvl==0 ? f0 : lvl==1 ? f1 : lvl==2 ? f2 : f3);
    size_t imgBase = (size_t)s_img * H * H * C_CH;
    int c4 = (threadIdx.x & 63) << 2;
    int bq = threadIdx.x >> 6;
    size_t outBase = (size_t)r * FEAT;

    for (int b = bq; b < 49; b += 4) {
        float wx = s_wx[b], wy = s_wy[b];
        size_t row0 = imgBase + (size_t)s_y0[b] * H * C_CH;
        size_t row1 = imgBase + (size_t)s_y1[b] * H * C_CH;
        size_t cx0  = (size_t)s_x0[b] * C_CH + c4;
        size_t cx1  = (size_t)s_x1[b] * C_CH + c4;
        float4 v00 = *(const float4*)&fm[row0 + cx0];
        float4 v01 = *(const float4*)&fm[row0 + cx1];
        float4 v10 = *(const float4*)&fm[row1 + cx0];
        float4 v11 = *(const float4*)&fm[row1 + cx1];
        float w00 = (1.f-wx)*(1.f-wy), w01 = wx*(1.f-wy);
        float w10 = (1.f-wx)*wy,       w11 = wx*wy;
        float o0 = v00.x*w00 + v01.x*w01 + v10.x*w10 + v11.x*w11;
        float o1 = v00.y*w00 + v01.y*w01 + v10.y*w10 + v11.y*w11;
        float o2 = v00.z*w00 + v01.z*w01 + v10.z*w10 + v11.z*w11;
        float o3 = v00.w*w00 + v01.w*w01 + v10.w*w10 + v11.w*w11;
        __half h0,l0,h1,l1,h2,l2,h3,l3;
        split_h(o0,h0,l0); split_h(o1,h1,l1); split_h(o2,h2,l2); split_h(o3,h3,l3);
        uint2 ph, pl;
        ph.x = (uint32_t)__half_as_ushort(h0) | ((uint32_t)__half_as_ushort(h1) << 16);
        ph.y = (uint32_t)__half_as_ushort(h2) | ((uint32_t)__half_as_ushort(h3) << 16);
        pl.x = (uint32_t)__half_as_ushort(l0) | ((uint32_t)__half_as_ushort(l1) << 16);
        pl.y = (uint32_t)__half_as_ushort(l2) | ((uint32_t)__half_as_ushort(l3) << 16);
        *(uint2*)&g_x0h[outBase + b*C_CH + c4] = ph;
        *(uint2*)&g_x0l[outBase + b*C_CH + c4] = pl;
    }
}

/* ------------------ fused transpose + fp16 split ------------------------------------ */
__global__ void tsplit_all_kernel(const float* __restrict__ W0,
                                  const float* __restrict__ W1,
                                  const float* __restrict__ Wc,
                                  const float* __restrict__ Wr,
                                  int N0, int N1, int NC, int NR)
{
    __shared__ float tile[32][33];
    int by = blockIdx.y;
    const float* in; __half *outH, *outL;
    int K, N, roff, Kout, kseg;
    if (by < 392)      { in = W0; K = FEAT; N = N0; roff = 0;  Kout = FEAT; kseg = by;
                         outH = g_W0th; outL = g_W0tl; }
    else if (by < 424) { in = W1; K = N1;   N = N1; roff = 0;  Kout = N1;   kseg = by - 392;
                         outH = g_W1th; outL = g_W1tl; }
    else if (by < 456) { in = Wc; K = N1;   N = NC; roff = 0;  Kout = N1;   kseg = by - 424;
                         outH = g_Whth; outL = g_Whtl; }
    else               { in = Wr; K = N1;   N = NR; roff = NC; Kout = N1;   kseg = by - 456;
                         outH = g_Whth; outL = g_Whtl; }

    int k0 = kseg * 32, n0 = blockIdx.x * 32;
    if (n0 >= N || k0 >= K) return;
    int tx = threadIdx.x, ty = threadIdx.y;
    #pragma unroll
    for (int j = 0; j < 4; j++) {
        int k = k0 + ty + j*8, n = n0 + tx;
        tile[ty + j*8][tx] = (k < K && n < N) ? in[(size_t)k * N + n] : 0.f;
    }
    __syncthreads();
    #pragma unroll
    for (int j = 0; j < 4; j++) {
        int n = n0 + ty + j*8, k = k0 + tx;
        if (n < N && k < Kout) {
            __half h, l; split_h(tile[tx][ty + j*8], h, l);
            size_t o = (size_t)(roff + n) * Kout + k;
            outH[o] = h;
            outL[o] = l;
        }
    }
}

__global__ void pack_bias_kernel(const float* __restrict__ bc, const float* __restrict__ br,
                                 int NC, int NR)
{
    int t = threadIdx.x;
    if (t < NC + NR)
        g_bhead[t] = (t < NC) ? bc[t] : br[t - NC];
}

/* ------------------ fp16x2 GEMM (round-12/14 proven: 3-stage, wait 1) --------------- */
#define B_OFF 16384
#define GSTG  24576
#define GT_STAGES 3
#define GT_DSMEM (GT_STAGES*GSTG)   /* 73728 */

__global__ __launch_bounds__(256, 2) void gemm_h2(
    const __half* __restrict__ Ah, const __half* __restrict__ Al,
    const __half* __restrict__ Bh, const __half* __restrict__ Bl,
    float* __restrict__ Cp, int M, int N, int K, int Ksl)
{
    extern __shared__ __align__(16) char sm[];
    uint32_t smb = smem_u32(sm);

    int tid = threadIdx.x, lane = tid & 31, warp = tid >> 5;
    int mBase = blockIdx.y * 128, nBase = blockIdx.x * 64;
    int kOff = blockIdx.z * Ksl;
    int wm = (warp & 3) * 32, wn = (warp >> 2) * 32;

    float acc[2][4][4];
    #pragma unroll
    for (int i = 0; i < 2; i++)
        #pragma unroll
        for (int j = 0; j < 4; j++)
            #pragma unroll
            for (int q = 0; q < 4; q++) acc[i][j][q] = 0.f;

    int Keff = K - kOff; if (Keff > Ksl) Keff = Ksl;
    int tiles = Keff >> 5;

    int arow0 = tid >> 2, akc0 = tid & 3;
    auto loadTile = [&](int t) {
        if (t < tiles) {
            int kt = kOff + (t << 5);
            uint32_t base = smb + (uint32_t)(t % GT_STAGES) * GSTG;
            #pragma unroll
            for (int i = 0; i < 2; i++) {
                int row = arow0 + i*64;
                size_t gi = (size_t)(mBase + row) * K + kt + akc0*8;
                uint32_t rb = base + (uint32_t)row*128u;
                uint32_t sw = (uint32_t)(row & 7);
                int sz = (mBase + row < M) ? 16 : 0;
                CPASYNC16(rb + ((((uint32_t)akc0*2u    ) ^ sw) << 4), Ah + gi, sz);
                CPASYNC16(rb + ((((uint32_t)akc0*2u + 1u) ^ sw) << 4), Al + gi, sz);
            }
            {
                int row = (tid >> 2) & 63;
                int kc  = akc0;
                size_t gi = (size_t)(nBase + row) * K + kt + kc*8;
                uint32_t rb = base + B_OFF + (uint32_t)row*128u;
                uint32_t sw = (uint32_t)(row & 7);
                int sz = (nBase + row < N) ? 16 : 0;
                CPASYNC16(rb + ((((uint32_t)kc*2u    ) ^ sw) << 4), Bh + gi, sz);
                CPASYNC16(rb + ((((uint32_t)kc*2u + 1u) ^ sw) << 4), Bl + gi, sz);
            }
        }
        asm volatile("cp.async.commit_group;");
    };

    loadTile(0); loadTile(1);

    int lm = lane >> 3, lr = lane & 7;
    uint32_t aSw = (uint32_t)lr;
    uint32_t akcb = (uint32_t)(lm >> 1);
    uint32_t bkcb = (uint32_t)(lm & 1);
    uint32_t aOffC[2][2], bOffC[2][2];
    #pragma unroll
    for (int ks = 0; ks < 2; ks++) {
        uint32_t cA = (akcb + (uint32_t)ks*2u) << 1;
        uint32_t cB = (bkcb + (uint32_t)ks*2u) << 1;
        aOffC[ks][0] = ((cA     ) ^ aSw) << 4;
        aOffC[ks][1] = ((cA | 1u) ^ aSw) << 4;
        bOffC[ks][0] = ((cB     ) ^ aSw) << 4;
        bOffC[ks][1] = ((cB | 1u) ^ aSw) << 4;
    }
    uint32_t aRow[2], bRow[2];
    #pragma unroll
    for (int mi = 0; mi < 2; mi++)
        aRow[mi] = (uint32_t)(wm + mi*16 + (lm&1)*8 + lr) * 128u;
    #pragma unroll
    for (int g = 0; g < 2; g++)
        bRow[g] = (uint32_t)B_OFF + (uint32_t)(wn + g*16 + (lm>>1)*8 + lr) * 128u;

    for (int t = 0; t < tiles; t++) {
        asm volatile("cp.async.wait_group 1;");
        __syncthreads();
        loadTile(t + 2);
        uint32_t base = smb + (uint32_t)(t % GT_STAGES) * GSTG;
        uint32_t a0 = base + aRow[0], a1 = base + aRow[1];
        uint32_t b0 = base + bRow[0], b1 = base + bRow[1];

        uint32_t ah[2][2][4], al[2][2][4];
        uint32_t bh[2][4][2], bl[2][4][2];
        #pragma unroll
        for (int ks = 0; ks < 2; ks++) {
            LDSM4(ah[ks][0][0], ah[ks][0][1], ah[ks][0][2], ah[ks][0][3], a0 + aOffC[ks][0]);
            LDSM4(al[ks][0][0], al[ks][0][1], al[ks][0][2], al[ks][0][3], a0 + aOffC[ks][1]);
            LDSM4(ah[ks][1][0], ah[ks][1][1], ah[ks][1][2], ah[ks][1][3], a1 + aOffC[ks][0]);
            LDSM4(al[ks][1][0], al[ks][1][1], al[ks][1][2], al[ks][1][3], a1 + aOffC[ks][1]);
            uint32_t r0, r1, r2, r3;
            LDSM4(r0, r1, r2, r3, b0 + bOffC[ks][0]);
            bh[ks][0][0]=r0; bh[ks][0][1]=r1; bh[ks][1][0]=r2; bh[ks][1][1]=r3;
            LDSM4(r0, r1, r2, r3, b0 + bOffC[ks][1]);
            bl[ks][0][0]=r0; bl[ks][0][1]=r1; bl[ks][1][0]=r2; bl[ks][1][1]=r3;
            LDSM4(r0, r1, r2, r3, b1 + bOffC[ks][0]);
            bh[ks][2][0]=r0; bh[ks][2][1]=r1; bh[ks][3][0]=r2; bh[ks][3][1]=r3;
            LDSM4(r0, r1, r2, r3, b1 + bOffC[ks][1]);
            bl[ks][2][0]=r0; bl[ks][2][1]=r1; bl[ks][3][0]=r2; bl[ks][3][1]=r3;
        }

        #pragma unroll
        for (int ks = 0; ks < 2; ks++) {
            #pragma unroll
            for (int mi = 0; mi < 2; mi++)
                #pragma unroll
                for (int nj = 0; nj < 4; nj++)
                    MMA16816(acc[mi][nj], ah[ks][mi], bh[ks][nj]);
            #pragma unroll
            for (int mi = 0; mi < 2; mi++)
                #pragma unroll
                for (int nj = 0; nj < 4; nj++)
                    MMA16816(acc[mi][nj], ah[ks][mi], bl[ks][nj]);
            #pragma unroll
            for (int mi = 0; mi < 2; mi++)
                #pragma unroll
                for (int nj = 0; nj < 4; nj++)
                    MMA16816(acc[mi][nj], al[ks][mi], bh[ks][nj]);
        }
    }

    /* epilogue: raw fp32 partial */
    float* out = Cp + (size_t)blockIdx.z * M * N;
    #pragma unroll
    for (int mi = 0; mi < 2; mi++) {
        #pragma unroll
        for (int nj = 0; nj < 4; nj++) {
            #pragma unroll
            for (int q = 0; q < 4; q++) {
                int row = mBase + wm + mi*16 + (lane >> 2) + (q >> 1)*8;
                int col = nBase + wn + nj*8 + ((lane & 3) << 1) + (q & 1);
                if (row < M && col < N)
                    out[(size_t)row * N + col] = acc[mi][nj][q];
            }
        }
    }
}

/* ------------------ split-K reduce (float4 fast path when N%4==0) ------------------- */
__global__ void reduce_kernel(const float* __restrict__ part, const float* __restrict__ bias,
                              int M, int N, int nsl, int relu,
                              float* __restrict__ outF,
                              __half* __restrict__ outH, __half* __restrict__ outL)
{
    size_t total = (size_t)M * N;
    if ((N & 3) == 0) {
        size_t base = ((size_t)blockIdx.x * blockDim.x + threadIdx.x) * 4;
        if (base >= total) return;
        int col = (int)(base % (size_t)N);
        float4 v = *(const float4*)&bias[col];
        for (int s = 0; s < nsl; s++) {
            float4 p = *(const float4*)&part[(size_t)s * total + base];
            v.x += p.x; v.y += p.y; v.z += p.z; v.w += p.w;
        }
        if (relu) {
            v.x = fmaxf(v.x, 0.f); v.y = fmaxf(v.y, 0.f);
            v.z = fmaxf(v.z, 0.f); v.w = fmaxf(v.w, 0.f);
            __half h0,l0,h1,l1,h2,l2,h3,l3;
            split_h(v.x,h0,l0); split_h(v.y,h1,l1); split_h(v.z,h2,l2); split_h(v.w,h3,l3);
            uint2 ph, pl;
            ph.x = (uint32_t)__half_as_ushort(h0) | ((uint32_t)__half_as_ushort(h1) << 16);
            ph.y = (uint32_t)__half_as_ushort(h2) | ((uint32_t)__half_as_ushort(h3) << 16);
            pl.x = (uint32_t)__half_as_ushort(l0) | ((uint32_t)__half_as_ushort(l1) << 16);
            pl.y = (uint32_t)__half_as_ushort(l2) | ((uint32_t)__half_as_ushort(l3) << 16);
            *(uint2*)&outH[base] = ph;
            *(uint2*)&outL[base] = pl;
        } else {
            *(float4*)&outF[base] = v;
        }
    } else {
        size_t idx = (size_t)blockIdx.x * blockDim.x + threadIdx.x;
        if (idx >= total) return;
        int col = (int)(idx % (size_t)N);
        float v = bias[col];
        for (int s = 0; s < nsl; s++) v += part[(size_t)s * total + idx];
        if (relu) {
            v = fmaxf(v, 0.f);
            __half h, l; split_h(v, h, l);
            outH[idx] = h;
            outL[idx] = l;
        } else {
            outF[idx] = v;
        }
    }
}

/* ------------------ softmax + box decode (parallel reductions) ---------------------- */
__global__ void decode_kernel(const float* __restrict__ prop,
                              const int*   __restrict__ imidx,
                              const float* __restrict__ imsizes,
                              const float* __restrict__ sthr_p,
                              const float* __restrict__ minsz_p,
                              int NC, int NT)
{
    int r = blockIdx.x;
    int t = threadIdx.x;
    int lane = t & 31, warp = t >> 5;
    __shared__ float sl[128];
    __shared__ float wred[4];
    __shared__ float smax, ssum;

    const float* head = &g_headout[(size_t)r * NT];

    float v = (t < NC) ? head[t] : -3.0e38f;
    sl[t] = v;
    /* block max via shfl + 4-word combine */
    float m = v;
    #pragma unroll
    for (int o = 16; o; o >>= 1) m = fmaxf(m, __shfl_xor_sync(0xffffffffu, m, o));
    if (lane == 0) wred[warp] = m;
    __syncthreads();
    if (t == 0) {
        float mm = fmaxf(fmaxf(wred[0], wred[1]), fmaxf(wred[2], wred[3]));
        smax = mm;
    }
    __syncthreads();
    float e = (t < NC) ? expf(v - smax) : 0.f;
    if (t < NC) sl[t] = e;
    float s = e;
    #pragma unroll
    for (int o = 16; o; o >>= 1) s += __shfl_xor_sync(0xffffffffu, s, o);
    if (lane == 0) wred[warp] = s;
    __syncthreads();
    if (t == 0) ssum = wred[0] + wred[1] + wred[2] + wred[3];
    __syncthreads();

    int D = NC - 1;
    if (t < D) {
        float score = sl[t+1] / ssum;
        float px1 = prop[r*4+0], py1 = prop[r*4+1];
        float px2 = prop[r*4+2], py2 = prop[r*4+3];
        float pw = px2 - px1, ph = py2 - py1;
        float cx = (px1 + px2)*0.5f, cy = (py1 + py2)*0.5f;
        const float* rg = &head[NC + (t+1)*4];
        float dx = rg[0]*0.1f, dy = rg[1]*0.1f;
        float dw = fminf(rg[2]*0.2f, LOG_MAX_CONST);
        float dh = fminf(rg[3]*0.2f, LOG_MAX_CONST);
        float ncx = dx*pw + cx, ncy = dy*ph + cy;
        float nw  = expf(dw)*pw, nh  = expf(dh)*ph;
        int im = imidx[r];
        float hb = imsizes[im*2+0], wb = imsizes[im*2+1];
        float bx1 = fminf(fmaxf(ncx - nw*0.5f, 0.f), wb);
        float bx2 = fminf(fmaxf(ncx + nw*0.5f, 0.f), wb);
        float by1 = fminf(fmaxf(ncy - nh*0.5f, 0.f), hb);
        float by2 = fminf(fmaxf(ncy + nh*0.5f, 0.f), hb);
        float sthr = *sthr_p, minsz = *minsz_p;
        bool valid = (score > sthr) && (bx2 - bx1 >= minsz) && (by2 - by1 >= minsz);
        int m2 = r*D + t;
        g_cscore[m2] = valid ? score : -1.0f;
        g_cbox[m2]   = make_float4(bx1, by1, bx2, by2);
    }
}

/* ------------------ two-phase deterministic compaction ------------------------------ */
#define CCH 4096
__global__ void compact_count_kernel(const int* __restrict__ imidx, int M, int D)
{
    int chunk = blockIdx.x, img = blockIdx.y;
    int tid = threadIdx.x, lane = tid & 31, wid = tid >> 5;
    __shared__ int wsum[8];
    int base = chunk * CCH;
    int cnt = 0;
    #pragma unroll 4
    for (int j = 0; j < 16; j++) {
        int m = base + tid*16 + j;
        if (m < M) {
            float v = g_cscore[m];
            if (v > 0.f && imidx[m / D] == img) cnt++;
        }
    }
    #pragma unroll
    for (int o = 16; o; o >>= 1) cnt += __shfl_xor_sync(0xffffffffu, cnt, o);
    if (lane == 0) wsum[wid] = cnt;
    __syncthreads();
    if (tid == 0) {
        int s = 0;
        for (int w = 0; w < 8; w++) s += wsum[w];
        g_ccnt[img*32 + chunk] = s;
    }
}

__global__ void compact_scatter_kernel(const int* __restrict__ imidx, int M, int D, int nch)
{
    int chunk = blockIdx.x, img = blockIdx.y;
    int tid = threadIdx.x, lane = tid & 31, wid = tid >> 5;
    __shared__ int woff[8];
    __shared__ int sbase;
    if (tid == 0) {
        int s = 0;
        for (int c = 0; c < chunk; c++) s += g_ccnt[img*32 + c];
        sbase = s;
        if (chunk == nch - 1) g_cnt[img] = s + g_ccnt[img*32 + chunk];
    }
    int base = chunk * CCH;
    int cnt = 0; int mi[16]; float sv[16];
    for (int j = 0; j < 16; j++) {
        int m = base + tid*16 + j;
        if (m < M) {
            float v = g_cscore[m];
            if (v > 0.f && imidx[m / D] == img) { sv[cnt] = v; mi[cnt] = m; cnt++; }
        }
    }
    int pre = cnt;
    #pragma unroll
    for (int o = 1; o < 32; o <<= 1) {
        int x = __shfl_up_sync(0xffffffffu, pre, o);
        if (lane >= o) pre += x;
    }
    if (lane == 31) woff[wid] = pre;
    __syncthreads();
    int wbase = 0;
    for (int w = 0; w < wid; w++) wbase += woff[w];
    int p = sbase + wbase + pre - cnt;
    for (int q = 0; q < cnt; q++) {
        int m = mi[q];
        size_t o = (size_t)img*M_MAX + p + q;
        float4 b = g_cbox[m];
        g_score_c[o] = sv[q];
        g_box_c[o]   = b;
        g_area_c[o]  = (b.z - b.x)*(b.w - b.y);
        g_cls_c[o]   = (m % D) + 1;
    }
}

/* ------------------ sequential NMS -------------------------------------------------- */
#define NMS_CAP 32768
#define NMS_T   512
__global__ __launch_bounds__(NMS_T) void nms_kernel(const float* __restrict__ iou_p,
                                                    float* __restrict__ out,
                                                    int n, int imtop)
{
    extern __shared__ float ssc[];
    int img = blockIdx.x, tid = threadIdx.x;
    int lane = tid & 31, warp = tid >> 5;
    int K = g_cnt[img];
    float iouT = *iou_p;
    float*  gsc = &g_score_c[(size_t)img*M_MAX];
    float4* bx  = &g_box_c[(size_t)img*M_MAX];
    float*  ar  = &g_area_c[(size_t)img*M_MAX];
    int*    cl  = &g_cls_c[(size_t)img*M_MAX];

    bool useS = (K <= NMS_CAP);
    float* sc = useS ? ssc : gsc;
    if (useS) for (int k = tid; k < K; k += NMS_T) ssc[k] = gsc[k];

    __shared__ unsigned long long wred[NMS_T/32];
    __shared__ float4 shb; __shared__ float sha; __shared__ int shc, shi; __shared__ float shv;
    __syncthreads();

    float* oB = out + (size_t)img*imtop*4;
    float* oS = out + (size_t)n*imtop*4 + (size_t)img*imtop;
    float* oC = out + (size_t)n*imtop*5 + (size_t)img*imtop;

    int t = 0;
    for (; t < imtop; t++) {
        unsigned long long best = 0ull;
        for (int k = tid; k < K; k += NMS_T) {
            float v = sc[k];
            if (v > 0.f) {
                unsigned long long p =
                    ((unsigned long long)__float_as_uint(v) << 32) |
                    (unsigned)(0x7FFFFFFF - k);
                if (p > best) best = p;
            }
        }
        #pragma unroll
        for (int o = 16; o; o >>= 1) {
            unsigned long long q = __shfl_xor_sync(0xffffffffu, best, o);
            if (q > best) best = q;
        }
        if (lane == 0) wred[warp] = best;
        __syncthreads();
        if (warp == 0) {
            unsigned long long b2 = (lane < NMS_T/32) ? wred[lane] : 0ull;
            #pragma unroll
            for (int o = 8; o; o >>= 1) {
                unsigned long long q = __shfl_xor_sync(0xffffffffu, b2, o);
                if (q > b2) b2 = q;
            }
            if (lane == 0) {
                if (b2) {
                    int wi = 0x7FFFFFFF - (int)(unsigned)(b2 & 0xFFFFFFFFu);
                    shv = __uint_as_float((unsigned)(b2 >> 32));
                    shi = wi; shb = bx[wi]; sha = ar[wi]; shc = cl[wi];
                } else {
                    shv = -1.f;
                }
            }
        }
        __syncthreads();
        float wv = shv;
        if (wv <= 0.f) break;
        int wi = shi; float4 wb = shb; float wa = sha; int wc = shc;
        for (int k = tid; k < K; k += NMS_T) {
            float v = sc[k];
            if (v <= 0.f) continue;
            if (k == wi) { sc[k] = -1.f; continue; }
            if (cl[k] != wc) continue;
            float4 b = bx[k];
            float iw = fmaxf(fminf(wb.z, b.z) - fmaxf(wb.x, b.x), 0.f);
            float ih = fmaxf(fminf(wb.w, b.w) - fmaxf(wb.y, b.y), 0.f);
            float inter = iw * ih;
            float iou = inter / (wa + ar[k] - inter + 1e-6f);
            if (iou > iouT) sc[k] = -1.f;
        }
        if (tid == 0) {
            oB[t*4+0] = wb.x; oB[t*4+1] = wb.y; oB[t*4+2] = wb.z; oB[t*4+3] = wb.w;
            oS[t] = wv;
            oC[t] = (float)wc;
        }
        __syncthreads();
    }
    for (int u = t + tid; u < imtop; u += NMS_T) {
        oB[u*4+0] = 0.f; oB[u*4+1] = 0.f; oB[u*4+2] = 0.f; oB[u*4+3] = 0.f;
        oS[u] = 0.f;
        oC[u] = -1.f;
    }
}

/* ------------------ host launch ---------------------------------------------------- */
extern "C" void kernel_launch(void* const* d_in, const int* in_sizes, int n_in,
                              void* d_out, int out_size)
{
    const float* prop    = (const float*)d_in[0];
    const int*   imidx   = (const int*)  d_in[1];
    const float* f0      = (const float*)d_in[2];
    const float* f1      = (const float*)d_in[3];
    const float* f2      = (const float*)d_in[4];
    const float* f3      = (const float*)d_in[5];
    const float* W0      = (const float*)d_in[6];
    const float* b0      = (const float*)d_in[7];
    const float* W1      = (const float*)d_in[8];
    const float* b1      = (const float*)d_in[9];
    const float* Wc      = (const float*)d_in[10];
    const float* bc      = (const float*)d_in[11];
    const float* Wr      = (const float*)d_in[12];
    const float* br      = (const float*)d_in[13];
    const float* imsizes = (const float*)d_in[14];
    const float* sthr    = (const float*)d_in[15];
    const float* iouthr  = (const float*)d_in[16];
    const float* minsz   = (const float*)d_in[18];

    int R  = in_sizes[0] / 4;
    int n  = in_sizes[14] / 2;
    int imtop = out_size / (6 * n);
    int N0 = in_sizes[7];
    int N1 = in_sizes[9];
    int NC = in_sizes[11];
    int NR = in_sizes[13];
    int NT = NC + NR;
    int D  = NC - 1;
    int M  = R * D;

    int H0 = (int)(sqrt((double)in_sizes[2] / ((double)n * C_CH)) + 0.5);
    int H1 = (int)(sqrt((double)in_sizes[3] / ((double)n * C_CH)) + 0.5);
    int H2 = (int)(sqrt((double)in_sizes[4] / ((double)n * C_CH)) + 0.5);
    int H3 = (int)(sqrt((double)in_sizes[5] / ((double)n * C_CH)) + 0.5);

    __half *px0h, *px0l, *pW0h, *pW0l, *pW1h, *pW1l, *pWhh, *pWhl;
    __half *px1h, *px1l, *px2h, *px2l;
    float *phead, *pbh, *ppart;
    cudaGetSymbolAddress((void**)&px0h, g_x0h);  cudaGetSymbolAddress((void**)&px0l, g_x0l);
    cudaGetSymbolAddress((void**)&pW0h, g_W0th); cudaGetSymbolAddress((void**)&pW0l, g_W0tl);
    cudaGetSymbolAddress((void**)&pW1h, g_W1th); cudaGetSymbolAddress((void**)&pW1l, g_W1tl);
    cudaGetSymbolAddress((void**)&pWhh, g_Whth); cudaGetSymbolAddress((void**)&pWhl, g_Whtl);
    cudaGetSymbolAddress((void**)&px1h, g_x1h);  cudaGetSymbolAddress((void**)&px1l, g_x1l);
    cudaGetSymbolAddress((void**)&px2h, g_x2h);  cudaGetSymbolAddress((void**)&px2l, g_x2l);
    cudaGetSymbolAddress((void**)&phead, g_headout);
    cudaGetSymbolAddress((void**)&pbh,   g_bhead);
    cudaGetSymbolAddress((void**)&ppart, g_part);

    cudaFuncSetAttribute(gemm_h2, cudaFuncAttributeMaxDynamicSharedMemorySize, GT_DSMEM);
    cudaFuncSetAttribute(nms_kernel, cudaFuncAttributeMaxDynamicSharedMemorySize, NMS_CAP*4);

    static cudaStream_t s2 = nullptr;
    static cudaEvent_t evFork = nullptr, evJoin = nullptr;
    if (!s2) {
        cudaStreamCreateWithFlags(&s2, cudaStreamNonBlocking);
        cudaEventCreateWithFlags(&evFork, cudaEventDisableTiming);
        cudaEventCreateWithFlags(&evJoin, cudaEventDisableTiming);
    }

    cudaEventRecord(evFork, 0);
    cudaStreamWaitEvent(s2, evFork, 0);

    /* 1. ROI align (stream 0) || weight prep (stream s2) */
    roi_align_kernel<<<R, 256>>>(prop, imidx, f0, f1, f2, f3, H0, H1, H2, H3);
    {
        dim3 b(32, 8);
        tsplit_all_kernel<<<dim3(32, 488), b, 0, s2>>>(W0, W1, Wc, Wr, N0, N1, NC, NR);
        pack_bias_kernel<<<1, 512, 0, s2>>>(bc, br, NC, NR);
    }
    cudaEventRecord(evJoin, s2);
    cudaStreamWaitEvent(0, evJoin, 0);

    int rdT = 256;

    /* 2. FC1 (FEAT->N0): split-K x7 (Ksl=1792; grid 896 = 3.03 waves) */
    {
        dim3 g((N0 + 63)/64, (R + 127)/128, 7);
        gemm_h2<<<g, 256, GT_DSMEM>>>(px0h, px0l, pW0h, pW0l, ppart, R, N0, FEAT, 1792);
        size_t tot = (size_t)R * N0;
        int thr = (int)((N0 & 3) == 0 ? (tot + 3)/4 : tot);
        reduce_kernel<<<(thr + rdT - 1)/rdT, rdT>>>(ppart, b0, R, N0, 7, 1,
                                                    nullptr, px1h, px1l);
    }
    /* 3. FC2 (N0->N1): split-K x2 (grid 256, single wave) */
    {
        dim3 g((N1 + 63)/64, (R + 127)/128, 2);
        gemm_h2<<<g, 256, GT_DSMEM>>>(px1h, px1l, pW1h, pW1l, ppart, R, N1, N0, 512);
        size_t tot = (size_t)R * N1;
        int thr = (int)((N1 & 3) == 0 ? (tot + 3)/4 : tot);
        reduce_kernel<<<(thr + rdT - 1)/rdT, rdT>>>(ppart, b1, R, N1, 2, 1,
                                                    nullptr, px2h, px2l);
    }
    /* 4. fused class+reg head (N1->NT): split-K x5 (grid 280 ~ one wave) */
    {
        dim3 g((NT + 63)/64, (R + 127)/128, 5);
        gemm_h2<<<g, 256, GT_DSMEM>>>(px2h, px2l, pWhh, pWhl, ppart, R, NT, N1, 224);
        size_t tot = (size_t)R * NT;
        int thr = (int)((NT & 3) == 0 ? (tot + 3)/4 : tot);
        reduce_kernel<<<(thr + rdT - 1)/rdT, rdT>>>(ppart, pbh, R, NT, 5, 0,
                                                    phead, nullptr, nullptr);
    }
    /* 5. softmax + box decode */
    decode_kernel<<<R, 128>>>(prop, imidx, imsizes, sthr, minsz, NC, NT);

    /* 6. two-phase deterministic compaction */
    {
        int nch = (M + CCH - 1) / CCH;
        compact_count_kernel<<<dim3(nch, n), 256>>>(imidx, M, D);
        compact_scatter_kernel<<<dim3(nch, n), 256>>>(imidx, M, D, nch);
    }

    /* 7. sequential NMS + output write */
    nms_kernel<<<n, NMS_T, NMS_CAP*4>>>(iouthr, (float*)d_out, n, imtop);
}

// round 17
// speedup vs baseline: 1.0378x; 1.0173x over previous
#include <cuda_runtime.h>
#include <cuda_fp16.h>
#include <math.h>
#include <stdint.h>

#define C_CH 256
#define POOL 7
#define FEAT (POOL*POOL*C_CH)      /* 12544 */
#define R_MAX 1024
#define DCLS_MAX 80
#define M_MAX (R_MAX*DCLS_MAX)
#define NIMG_MAX 4
#define NHEAD_MAX 408
#define LOG_MAX_CONST 4.1351665567423556f

/* ------------------ scratch ---------------------------------------------------------- */
__device__ __half g_x0h[(size_t)R_MAX*FEAT];
__device__ __half g_x0l[(size_t)R_MAX*FEAT];
__device__ __half g_W0th[(size_t)1024*FEAT];
__device__ __half g_W0tl[(size_t)1024*FEAT];
__device__ __half g_W1th[(size_t)1024*1024];
__device__ __half g_W1tl[(size_t)1024*1024];
__device__ __half g_Whth[(size_t)NHEAD_MAX*1024];
__device__ __half g_Whtl[(size_t)NHEAD_MAX*1024];
__device__ __half g_x1h[(size_t)R_MAX*1024];
__device__ __half g_x1l[(size_t)R_MAX*1024];
__device__ __half g_x2h[(size_t)R_MAX*1024];
__device__ __half g_x2l[(size_t)R_MAX*1024];
__device__ float  g_part[(size_t)8*R_MAX*1024];
__device__ float  g_headout[(size_t)R_MAX*NHEAD_MAX];
__device__ float  g_bhead[NHEAD_MAX];
__device__ float  g_cscore[M_MAX];
__device__ float4 g_cbox[M_MAX];
__device__ float  g_score_c[(size_t)NIMG_MAX*M_MAX];
__device__ float4 g_box_c[(size_t)NIMG_MAX*M_MAX];
__device__ float  g_area_c[(size_t)NIMG_MAX*M_MAX];
__device__ int    g_cls_c[(size_t)NIMG_MAX*M_MAX];
__device__ int    g_cnt[NIMG_MAX];
__device__ int    g_ccnt[NIMG_MAX*32];

/* ------------------ helpers --------------------------------------------------------- */
__device__ __forceinline__ uint32_t smem_u32(const void* p) {
    uint32_t a;
    asm("{ .reg .u64 t; cvta.to.shared.u64 t, %1; cvt.u32.u64 %0, t; }" : "=r"(a) : "l"(p));
    return a;
}
__device__ __forceinline__ void split_h(float v, __half& hi, __half& lo)
{
    hi = __float2half_rn(v);
    lo = __float2half_rn(v - __half2float(hi));
}

#define LDSM4(r0,r1,r2,r3, addr) \
    asm volatile("ldmatrix.sync.aligned.m8n8.x4.shared.b16 {%0,%1,%2,%3}, [%4];" \
        : "=r"(r0),"=r"(r1),"=r"(r2),"=r"(r3) : "r"(addr))

#define MMA16816(d, a, b) \
    asm volatile("mma.sync.aligned.m16n8k16.row.col.f32.f16.f16.f32 " \
        "{%0,%1,%2,%3}, {%4,%5,%6,%7}, {%8,%9}, {%0,%1,%2,%3};" \
        : "+f"((d)[0]), "+f"((d)[1]), "+f"((d)[2]), "+f"((d)[3]) \
        : "r"((a)[0]), "r"((a)[1]), "r"((a)[2]), "r"((a)[3]), "r"((b)[0]), "r"((b)[1]))

#define CPASYNC16(dst, src, sz) \
    asm volatile("cp.async.ca.shared.global [%0], [%1], 16, %2;" \
        :: "r"(dst), "l"(src), "r"(sz))

/* ------------------ ROI align: 2 bins interleaved per iteration --------------------- */
__global__ void roi_align_kernel(const float* __restrict__ prop,
                                 const int*   __restrict__ imidx,
                                 const float* __restrict__ f0, const float* __restrict__ f1,
                                 const float* __restrict__ f2, const float* __restrict__ f3,
                                 int H0, int H1, int H2, int H3)
{
    int r = blockIdx.x;
    __shared__ int   s_lvl, s_img, s_H;
    __shared__ int   s_y0[49], s_y1[49], s_x0[49], s_x1[49];
    __shared__ float s_wx[49], s_wy[49];

    if (threadIdx.x == 0) {
        float x1 = prop[r*4+0], y1 = prop[r*4+1], x2 = prop[r*4+2], y2 = prop[r*4+3];
        float pw = x2 - x1, ph = y2 - y1;
        float l = floorf(4.0f + log2f(sqrtf(pw*ph) / 224.0f + 1e-6f));
        l = fminf(fmaxf(l, 2.0f), 5.0f);
        int lvl = (int)l - 2;
        s_lvl = lvl;
        s_img = imidx[r];
        s_H   = (lvl==0 ? H0 : lvl==1 ? H1 : lvl==2 ? H2 : H3);
    }
    __syncthreads();
    int lvl = s_lvl, H = s_H;

    if (threadIdx.x < 49) {
        int py = threadIdx.x / 7, px = threadIdx.x % 7;
        float s  = 1.0f / (float)(4 << lvl);
        float x1 = prop[r*4+0]*s, y1 = prop[r*4+1]*s;
        float x2 = prop[r*4+2]*s, y2 = prop[r*4+3]*s;
        float gx = (px + 0.5f) / (float)POOL;
        float gy = (py + 0.5f) / (float)POOL;
        float xx = x1 + gx*(x2 - x1) - 0.5f;
        float yy = y1 + gy*(y2 - y1) - 0.5f;
        float x0f = floorf(xx), y0f = floorf(yy);
        s_wx[threadIdx.x] = xx - x0f;
        s_wy[threadIdx.x] = yy - y0f;
        int xi = (int)x0f, yi = (int)y0f;
        s_x0[threadIdx.x] = min(max(xi,     0), H-1);
        s_x1[threadIdx.x] = min(max(xi + 1, 0), H-1);
        s_y0[threadIdx.x] = min(max(yi,     0), H-1);
        s_y1[threadIdx.x] = min(max(yi + 1, 0), H-1);
    }
    __syncthreads();

    const float* fm = (lvl==0 ? f0 : lvl==1 ? f1 : lvl==2 ? f2 : f3);
    size_t imgBase = (size_t)s_img * H * H * C_CH;
    int c4 = (threadIdx.x & 63) << 2;
    int bq = threadIdx.x >> 6;
    size_t outBase = (size_t)r * FEAT;

    for (int b = bq; b < 49; b += 8) {
        int bB = b + 4;
        bool hasB = bB < 49;

        /* issue all 8 loads before consuming (doubled MLP) */
        size_t ra0 = imgBase + (size_t)s_y0[b] * H * C_CH;
        size_t ra1 = imgBase + (size_t)s_y1[b] * H * C_CH;
        size_t ca0 = (size_t)s_x0[b] * C_CH + c4;
        size_t ca1 = (size_t)s_x1[b] * C_CH + c4;
        float4 a00 = *(const float4*)&fm[ra0 + ca0];
        float4 a01 = *(const float4*)&fm[ra0 + ca1];
        float4 a10 = *(const float4*)&fm[ra1 + ca0];
        float4 a11 = *(const float4*)&fm[ra1 + ca1];

        int bS = hasB ? bB : b;
        size_t rb0 = imgBase + (size_t)s_y0[bS] * H * C_CH;
        size_t rb1 = imgBase + (size_t)s_y1[bS] * H * C_CH;
        size_t cb0 = (size_t)s_x0[bS] * C_CH + c4;
        size_t cb1 = (size_t)s_x1[bS] * C_CH + c4;
        float4 q00 = *(const float4*)&fm[rb0 + cb0];
        float4 q01 = *(const float4*)&fm[rb0 + cb1];
        float4 q10 = *(const float4*)&fm[rb1 + cb0];
        float4 q11 = *(const float4*)&fm[rb1 + cb1];

        {
            float wx = s_wx[b], wy = s_wy[b];
            float w00 = (1.f-wx)*(1.f-wy), w01 = wx*(1.f-wy);
            float w10 = (1.f-wx)*wy,       w11 = wx*wy;
            float o0 = a00.x*w00 + a01.x*w01 + a10.x*w10 + a11.x*w11;
            float o1 = a00.y*w00 + a01.y*w01 + a10.y*w10 + a11.y*w11;
            float o2 = a00.z*w00 + a01.z*w01 + a10.z*w10 + a11.z*w11;
            float o3 = a00.w*w00 + a01.w*w01 + a10.w*w10 + a11.w*w11;
            __half h0,l0,h1,l1,h2,l2,h3,l3;
            split_h(o0,h0,l0); split_h(o1,h1,l1); split_h(o2,h2,l2); split_h(o3,h3,l3);
            uint2 ph, pl;
            ph.x = (uint32_t)__half_as_ushort(h0) | ((uint32_t)__half_as_ushort(h1) << 16);
            ph.y = (uint32_t)__half_as_ushort(h2) | ((uint32_t)__half_as_ushort(h3) << 16);
            pl.x = (uint32_t)__half_as_ushort(l0) | ((uint32_t)__half_as_ushort(l1) << 16);
            pl.y = (uint32_t)__half_as_ushort(l2) | ((uint32_t)__half_as_ushort(l3) << 16);
            *(uint2*)&g_x0h[outBase + b*C_CH + c4] = ph;
            *(uint2*)&g_x0l[outBase + b*C_CH + c4] = pl;
        }
        if (hasB) {
            float wx = s_wx[bB], wy = s_wy[bB];
            float w00 = (1.f-wx)*(1.f-wy), w01 = wx*(1.f-wy);
            float w10 = (1.f-wx)*wy,       w11 = wx*wy;
            float o0 = q00.x*w00 + q01.x*w01 + q10.x*w10 + q11.x*w11;
            float o1 = q00.y*w00 + q01.y*w01 + q10.y*w10 + q11.y*w11;
            float o2 = q00.z*w00 + q01.z*w01 + q10.z*w10 + q11.z*w11;
            float o3 = q00.w*w00 + q01.w*w01 + q10.w*w10 + q11.w*w11;
            __half h0,l0,h1,l1,h2,l2,h3,l3;
            split_h(o0,h0,l0); split_h(o1,h1,l1); split_h(o2,h2,l2); split_h(o3,h3,l3);
            uint2 ph, pl;
            ph.x = (uint32_t)__half_as_ushort(h0) | ((uint32_t)__half_as_ushort(h1) << 16);
            ph.y = (uint32_t)__half_as_ushort(h2) | ((uint32_t)__half_as_ushort(h3) << 16);
            pl.x = (uint32_t)__half_as_ushort(l0) | ((uint32_t)__half_as_ushort(l1) << 16);
            pl.y = (uint32_t)__half_as_ushort(l2) | ((uint32_t)__half_as_ushort(l3) << 16);
            *(uint2*)&g_x0h[outBase + bB*C_CH + c4] = ph;
            *(uint2*)&g_x0l[outBase + bB*C_CH + c4] = pl;
        }
    }
}

/* ------------------ fused transpose + fp16 split ------------------------------------ */
__global__ void tsplit_all_kernel(const float* __restrict__ W0,
                                  const float* __restrict__ W1,
                                  const float* __restrict__ Wc,
                                  const float* __restrict__ Wr,
                                  int N0, int N1, int NC, int NR)
{
    __shared__ float tile[32][33];
    int by = blockIdx.y;
    const float* in; __half *outH, *outL;
    int K, N, roff, Kout, kseg;
    if (by < 392)      { in = W0; K = FEAT; N = N0; roff = 0;  Kout = FEAT; kseg = by;
                         outH = g_W0th; outL = g_W0tl; }
    else if (by < 424) { in = W1; K = N1;   N = N1; roff = 0;  Kout = N1;   kseg = by - 392;
                         outH = g_W1th; outL = g_W1tl; }
    else if (by < 456) { in = Wc; K = N1;   N = NC; roff = 0;  Kout = N1;   kseg = by - 424;
                         outH = g_Whth; outL = g_Whtl; }
    else               { in = Wr; K = N1;   N = NR; roff = NC; Kout = N1;   kseg = by - 456;
                         outH = g_Whth; outL = g_Whtl; }

    int k0 = kseg * 32, n0 = blockIdx.x * 32;
    if (n0 >= N || k0 >= K) return;
    int tx = threadIdx.x, ty = threadIdx.y;
    #pragma unroll
    for (int j = 0; j < 4; j++) {
        int k = k0 + ty + j*8, n = n0 + tx;
        tile[ty + j*8][tx] = (k < K && n < N) ? in[(size_t)k * N + n] : 0.f;
    }
    __syncthreads();
    #pragma unroll
    for (int j = 0; j < 4; j++) {
        int n = n0 + ty + j*8, k = k0 + tx;
        if (n < N && k < Kout) {
            __half h, l; split_h(tile[tx][ty + j*8], h, l);
            size_t o = (size_t)(roff + n) * Kout + k;
            outH[o] = h;
            outL[o] = l;
        }
    }
}

__global__ void pack_bias_kernel(const float* __restrict__ bc, const float* __restrict__ br,
                                 int NC, int NR)
{
    int t = threadIdx.x;
    if (t < NC + NR)
        g_bhead[t] = (t < NC) ? bc[t] : br[t - NC];
    if (t < NIMG_MAX*32) g_ccnt[t] = 0;   /* zero chunk counters for fused count */
}

/* ------------------ fp16x2 GEMM (proven: 3-stage, wait 1) --------------------------- */
#define B_OFF 16384
#define GSTG  24576
#define GT_STAGES 3
#define GT_DSMEM (GT_STAGES*GSTG)   /* 73728 */

__global__ __launch_bounds__(256, 2) void gemm_h2(
    const __half* __restrict__ Ah, const __half* __restrict__ Al,
    const __half* __restrict__ Bh, const __half* __restrict__ Bl,
    float* __restrict__ Cp, int M, int N, int K, int Ksl)
{
    extern __shared__ __align__(16) char sm[];
    uint32_t smb = smem_u32(sm);

    int tid = threadIdx.x, lane = tid & 31, warp = tid >> 5;
    int mBase = blockIdx.y * 128, nBase = blockIdx.x * 64;
    int kOff = blockIdx.z * Ksl;
    int wm = (warp & 3) * 32, wn = (warp >> 2) * 32;

    float acc[2][4][4];
    #pragma unroll
    for (int i = 0; i < 2; i++)
        #pragma unroll
        for (int j = 0; j < 4; j++)
            #pragma unroll
            for (int q = 0; q < 4; q++) acc[i][j][q] = 0.f;

    int Keff = K - kOff; if (Keff > Ksl) Keff = Ksl;
    int tiles = Keff >> 5;

    int arow0 = tid >> 2, akc0 = tid & 3;
    auto loadTile = [&](int t) {
        if (t < tiles) {
            int kt = kOff + (t << 5);
            uint32_t base = smb + (uint32_t)(t % GT_STAGES) * GSTG;
            #pragma unroll
            for (int i = 0; i < 2; i++) {
                int row = arow0 + i*64;
                size_t gi = (size_t)(mBase + row) * K + kt + akc0*8;
                uint32_t rb = base + (uint32_t)row*128u;
                uint32_t sw = (uint32_t)(row & 7);
                int sz = (mBase + row < M) ? 16 : 0;
                CPASYNC16(rb + ((((uint32_t)akc0*2u    ) ^ sw) << 4), Ah + gi, sz);
                CPASYNC16(rb + ((((uint32_t)akc0*2u + 1u) ^ sw) << 4), Al + gi, sz);
            }
            {
                int row = (tid >> 2) & 63;
                int kc  = akc0;
                size_t gi = (size_t)(nBase + row) * K + kt + kc*8;
                uint32_t rb = base + B_OFF + (uint32_t)row*128u;
                uint32_t sw = (uint32_t)(row & 7);
                int sz = (nBase + row < N) ? 16 : 0;
                CPASYNC16(rb + ((((uint32_t)kc*2u    ) ^ sw) << 4), Bh + gi, sz);
                CPASYNC16(rb + ((((uint32_t)kc*2u + 1u) ^ sw) << 4), Bl + gi, sz);
            }
        }
        asm volatile("cp.async.commit_group;");
    };

    loadTile(0); loadTile(1);

    int lm = lane >> 3, lr = lane & 7;
    uint32_t aSw = (uint32_t)lr;
    uint32_t akcb = (uint32_t)(lm >> 1);
    uint32_t bkcb = (uint32_t)(lm & 1);
    uint32_t aOffC[2][2], bOffC[2][2];
    #pragma unroll
    for (int ks = 0; ks < 2; ks++) {
        uint32_t cA = (akcb + (uint32_t)ks*2u) << 1;
        uint32_t cB = (bkcb + (uint32_t)ks*2u) << 1;
        aOffC[ks][0] = ((cA     ) ^ aSw) << 4;
        aOffC[ks][1] = ((cA | 1u) ^ aSw) << 4;
        bOffC[ks][0] = ((cB     ) ^ aSw) << 4;
        bOffC[ks][1] = ((cB | 1u) ^ aSw) << 4;
    }
    uint32_t aRow[2], bRow[2];
    #pragma unroll
    for (int mi = 0; mi < 2; mi++)
        aRow[mi] = (uint32_t)(wm + mi*16 + (lm&1)*8 + lr) * 128u;
    #pragma unroll
    for (int g = 0; g < 2; g++)
        bRow[g] = (uint32_t)B_OFF + (uint32_t)(wn + g*16 + (lm>>1)*8 + lr) * 128u;

    for (int t = 0; t < tiles; t++) {
        asm volatile("cp.async.wait_group 1;");
        __syncthreads();
        loadTile(t + 2);
        uint32_t base = smb + (uint32_t)(t % GT_STAGES) * GSTG;
        uint32_t a0 = base + aRow[0], a1 = base + aRow[1];
        uint32_t b0 = base + bRow[0], b1 = base + bRow[1];

        uint32_t ah[2][2][4], al[2][2][4];
        uint32_t bh[2][4][2], bl[2][4][2];
        #pragma unroll
        for (int ks = 0; ks < 2; ks++) {
            LDSM4(ah[ks][0][0], ah[ks][0][1], ah[ks][0][2], ah[ks][0][3], a0 + aOffC[ks][0]);
            LDSM4(al[ks][0][0], al[ks][0][1], al[ks][0][2], al[ks][0][3], a0 + aOffC[ks][1]);
            LDSM4(ah[ks][1][0], ah[ks][1][1], ah[ks][1][2], ah[ks][1][3], a1 + aOffC[ks][0]);
            LDSM4(al[ks][1][0], al[ks][1][1], al[ks][1][2], al[ks][1][3], a1 + aOffC[ks][1]);
            uint32_t r0, r1, r2, r3;
            LDSM4(r0, r1, r2, r3, b0 + bOffC[ks][0]);
            bh[ks][0][0]=r0; bh[ks][0][1]=r1; bh[ks][1][0]=r2; bh[ks][1][1]=r3;
            LDSM4(r0, r1, r2, r3, b0 + bOffC[ks][1]);
            bl[ks][0][0]=r0; bl[ks][0][1]=r1; bl[ks][1][0]=r2; bl[ks][1][1]=r3;
            LDSM4(r0, r1, r2, r3, b1 + bOffC[ks][0]);
            bh[ks][2][0]=r0; bh[ks][2][1]=r1; bh[ks][3][0]=r2; bh[ks][3][1]=r3;
            LDSM4(r0, r1, r2, r3, b1 + bOffC[ks][1]);
            bl[ks][2][0]=r0; bl[ks][2][1]=r1; bl[ks][3][0]=r2; bl[ks][3][1]=r3;
        }

        #pragma unroll
        for (int ks = 0; ks < 2; ks++) {
            #pragma unroll
            for (int mi = 0; mi < 2; mi++)
                #pragma unroll
                for (int nj = 0; nj < 4; nj++)
                    MMA16816(acc[mi][nj], ah[ks][mi], bh[ks][nj]);
            #pragma unroll
            for (int mi = 0; mi < 2; mi++)
                #pragma unroll
                for (int nj = 0; nj < 4; nj++)
                    MMA16816(acc[mi][nj], ah[ks][mi], bl[ks][nj]);
            #pragma unroll
            for (int mi = 0; mi < 2; mi++)
                #pragma unroll
                for (int nj = 0; nj < 4; nj++)
                    MMA16816(acc[mi][nj], al[ks][mi], bh[ks][nj]);
        }
    }

    /* epilogue: raw fp32 partial */
    float* out = Cp + (size_t)blockIdx.z * M * N;
    #pragma unroll
    for (int mi = 0; mi < 2; mi++) {
        #pragma unroll
        for (int nj = 0; nj < 4; nj++) {
            #pragma unroll
            for (int q = 0; q < 4; q++) {
                int row = mBase + wm + mi*16 + (lane >> 2) + (q >> 1)*8;
                int col = nBase + wn + nj*8 + ((lane & 3) << 1) + (q & 1);
                if (row < M && col < N)
                    out[(size_t)row * N + col] = acc[mi][nj][q];
            }
        }
    }
}

/* ------------------ split-K reduce (float4 fast path when N%4==0) ------------------- */
__global__ void reduce_kernel(const float* __restrict__ part, const float* __restrict__ bias,
                              int M, int N, int nsl, int relu,
                              float* __restrict__ outF,
                              __half* __restrict__ outH, __half* __restrict__ outL)
{
    size_t total = (size_t)M * N;
    if ((N & 3) == 0) {
        size_t base = ((size_t)blockIdx.x * blockDim.x + threadIdx.x) * 4;
        if (base >= total) return;
        int col = (int)(base % (size_t)N);
        float4 v = *(const float4*)&bias[col];
        for (int s = 0; s < nsl; s++) {
            float4 p = *(const float4*)&part[(size_t)s * total + base];
            v.x += p.x; v.y += p.y; v.z += p.z; v.w += p.w;
        }
        if (relu) {
            v.x = fmaxf(v.x, 0.f); v.y = fmaxf(v.y, 0.f);
            v.z = fmaxf(v.z, 0.f); v.w = fmaxf(v.w, 0.f);
            __half h0,l0,h1,l1,h2,l2,h3,l3;
            split_h(v.x,h0,l0); split_h(v.y,h1,l1); split_h(v.z,h2,l2); split_h(v.w,h3,l3);
            uint2 ph, pl;
            ph.x = (uint32_t)__half_as_ushort(h0) | ((uint32_t)__half_as_ushort(h1) << 16);
            ph.y = (uint32_t)__half_as_ushort(h2) | ((uint32_t)__half_as_ushort(h3) << 16);
            pl.x = (uint32_t)__half_as_ushort(l0) | ((uint32_t)__half_as_ushort(l1) << 16);
            pl.y = (uint32_t)__half_as_ushort(l2) | ((uint32_t)__half_as_ushort(l3) << 16);
            *(uint2*)&outH[base] = ph;
            *(uint2*)&outL[base] = pl;
        } else {
            *(float4*)&outF[base] = v;
        }
    } else {
        size_t idx = (size_t)blockIdx.x * blockDim.x + threadIdx.x;
        if (idx >= total) return;
        int col = (int)(idx % (size_t)N);
        float v = bias[col];
        for (int s = 0; s < nsl; s++) v += part[(size_t)s * total + idx];
        if (relu) {
            v = fmaxf(v, 0.f);
            __half h, l; split_h(v, h, l);
            outH[idx] = h;
            outL[idx] = l;
        } else {
            outF[idx] = v;
        }
    }
}

/* ------------------ softmax + box decode + fused chunk counting --------------------- */
#define CCH 4096
__global__ void decode_kernel(const float* __restrict__ prop,
                              const int*   __restrict__ imidx,
                              const float* __restrict__ imsizes,
                              const float* __restrict__ sthr_p,
                              const float* __restrict__ minsz_p,
                              int NC, int NT)
{
    int r = blockIdx.x;
    int t = threadIdx.x;
    int lane = t & 31, warp = t >> 5;
    __shared__ float sl[128];
    __shared__ float wred[4];
    __shared__ float smax, ssum;

    const float* head = &g_headout[(size_t)r * NT];

    float v = (t < NC) ? head[t] : -3.0e38f;
    sl[t] = v;
    float m = v;
    #pragma unroll
    for (int o = 16; o; o >>= 1) m = fmaxf(m, __shfl_xor_sync(0xffffffffu, m, o));
    if (lane == 0) wred[warp] = m;
    __syncthreads();
    if (t == 0) smax = fmaxf(fmaxf(wred[0], wred[1]), fmaxf(wred[2], wred[3]));
    __syncthreads();
    float e = (t < NC) ? expf(v - smax) : 0.f;
    if (t < NC) sl[t] = e;
    float s = e;
    #pragma unroll
    for (int o = 16; o; o >>= 1) s += __shfl_xor_sync(0xffffffffu, s, o);
    if (lane == 0) wred[warp] = s;
    __syncthreads();
    if (t == 0) ssum = wred[0] + wred[1] + wred[2] + wred[3];
    __syncthreads();

    int D = NC - 1;
    bool valid = false;
    int mIdx = 0, img = 0;
    if (t < D) {
        float score = sl[t+1] / ssum;
        float px1 = prop[r*4+0], py1 = prop[r*4+1];
        float px2 = prop[r*4+2], py2 = prop[r*4+3];
        float pw = px2 - px1, ph = py2 - py1;
        float cx = (px1 + px2)*0.5f, cy = (py1 + py2)*0.5f;
        const float* rg = &head[NC + (t+1)*4];
        float dx = rg[0]*0.1f, dy = rg[1]*0.1f;
        float dw = fminf(rg[2]*0.2f, LOG_MAX_CONST);
        float dh = fminf(rg[3]*0.2f, LOG_MAX_CONST);
        float ncx = dx*pw + cx, ncy = dy*ph + cy;
        float nw  = expf(dw)*pw, nh  = expf(dh)*ph;
        img = imidx[r];
        float hb = imsizes[img*2+0], wb = imsizes[img*2+1];
        float bx1 = fminf(fmaxf(ncx - nw*0.5f, 0.f), wb);
        float bx2 = fminf(fmaxf(ncx + nw*0.5f, 0.f), wb);
        float by1 = fminf(fmaxf(ncy - nh*0.5f, 0.f), hb);
        float by2 = fminf(fmaxf(ncy + nh*0.5f, 0.f), hb);
        float sthr = *sthr_p, minsz = *minsz_p;
        valid = (score > sthr) && (bx2 - bx1 >= minsz) && (by2 - by1 >= minsz);
        mIdx = r*D + t;
        g_cscore[mIdx] = valid ? score : -1.0f;
        g_cbox[mIdx]   = make_float4(bx1, by1, bx2, by2);
    }

    /* fused chunk counting: warp-aggregated atomics (order-independent sums) */
    int myChunk = valid ? (mIdx / CCH) : -1;
    unsigned mask = __ballot_sync(0xffffffffu, valid);
    while (mask) {
        int leader = __ffs(mask) - 1;
        int lc = __shfl_sync(0xffffffffu, myChunk, leader);
        int li = __shfl_sync(0xffffffffu, img, leader);
        unsigned same = __ballot_sync(0xffffffffu, valid && myChunk == lc);
        if ((int)lane == leader)
            atomicAdd(&g_ccnt[li*32 + lc], (int)__popc(same));
        mask &= ~same;
    }
}

/* ------------------ compaction scatter (prefix from fused counts) ------------------- */
__global__ void compact_scatter_kernel(const int* __restrict__ imidx, int M, int D, int nch)
{
    int chunk = blockIdx.x, img = blockIdx.y;
    int tid = threadIdx.x, lane = tid & 31, wid = tid >> 5;
    __shared__ int woff[8];
    __shared__ int sbase;
    if (tid == 0) {
        int s = 0;
        for (int c = 0; c < chunk; c++) s += g_ccnt[img*32 + c];
        sbase = s;
        if (chunk == nch - 1) g_cnt[img] = s + g_ccnt[img*32 + chunk];
    }
    int base = chunk * CCH;
    int cnt = 0; int mi[16]; float sv[16];
    for (int j = 0; j < 16; j++) {
        int m = base + tid*16 + j;
        if (m < M) {
            float v = g_cscore[m];
            if (v > 0.f && imidx[m / D] == img) { sv[cnt] = v; mi[cnt] = m; cnt++; }
        }
    }
    int pre = cnt;
    #pragma unroll
    for (int o = 1; o < 32; o <<= 1) {
        int x = __shfl_up_sync(0xffffffffu, pre, o);
        if (lane >= o) pre += x;
    }
    if (lane == 31) woff[wid] = pre;
    __syncthreads();
    int wbase = 0;
    for (int w = 0; w < wid; w++) wbase += woff[w];
    int p = sbase + wbase + pre - cnt;
    for (int q = 0; q < cnt; q++) {
        int m = mi[q];
        size_t o = (size_t)img*M_MAX + p + q;
        float4 b = g_cbox[m];
        g_score_c[o] = sv[q];
        g_box_c[o]   = b;
        g_area_c[o]  = (b.z - b.x)*(b.w - b.y);
        g_cls_c[o]   = (m % D) + 1;
    }
}

/* ------------------ sequential NMS -------------------------------------------------- */
#define NMS_CAP 32768
#define NMS_T   512
__global__ __launch_bounds__(NMS_T) void nms_kernel(const float* __restrict__ iou_p,
                                                    float* __restrict__ out,
                                                    int n, int imtop)
{
    extern __shared__ float ssc[];
    int img = blockIdx.x, tid = threadIdx.x;
    int lane = tid & 31, warp = tid >> 5;
    int K = g_cnt[img];
    float iouT = *iou_p;
    float*  gsc = &g_score_c[(size_t)img*M_MAX];
    float4* bx  = &g_box_c[(size_t)img*M_MAX];
    float*  ar  = &g_area_c[(size_t)img*M_MAX];
    int*    cl  = &g_cls_c[(size_t)img*M_MAX];

    bool useS = (K <= NMS_CAP);
    float* sc = useS ? ssc : gsc;
    if (useS) for (int k = tid; k < K; k += NMS_T) ssc[k] = gsc[k];

    __shared__ unsigned long long wred[NMS_T/32];
    __shared__ float4 shb; __shared__ float sha; __shared__ int shc, shi; __shared__ float shv;
    __syncthreads();

    float* oB = out + (size_t)img*imtop*4;
    float* oS = out + (size_t)n*imtop*4 + (size_t)img*imtop;
    float* oC = out + (size_t)n*imtop*5 + (size_t)img*imtop;

    int t = 0;
    for (; t < imtop; t++) {
        unsigned long long best = 0ull;
        for (int k = tid; k < K; k += NMS_T) {
            float v = sc[k];
            if (v > 0.f) {
                unsigned long long p =
                    ((unsigned long long)__float_as_uint(v) << 32) |
                    (unsigned)(0x7FFFFFFF - k);
                if (p > best) best = p;
            }
        }
        #pragma unroll
        for (int o = 16; o; o >>= 1) {
            unsigned long long q = __shfl_xor_sync(0xffffffffu, best, o);
            if (q > best) best = q;
        }
        if (lane == 0) wred[warp] = best;
        __syncthreads();
        if (warp == 0) {
            unsigned long long b2 = (lane < NMS_T/32) ? wred[lane] : 0ull;
            #pragma unroll
            for (int o = 8; o; o >>= 1) {
                unsigned long long q = __shfl_xor_sync(0xffffffffu, b2, o);
                if (q > b2) b2 = q;
            }
            if (lane == 0) {
                if (b2) {
                    int wi = 0x7FFFFFFF - (int)(unsigned)(b2 & 0xFFFFFFFFu);
                    shv = __uint_as_float((unsigned)(b2 >> 32));
                    shi = wi; shb = bx[wi]; sha = ar[wi]; shc = cl[wi];
                } else {
                    shv = -1.f;
                }
            }
        }
        __syncthreads();
        float wv = shv;
        if (wv <= 0.f) break;
        int wi = shi; float4 wb = shb; float wa = sha; int wc = shc;
        for (int k = tid; k < K; k += NMS_T) {
            float v = sc[k];
            if (v <= 0.f) continue;
            if (k == wi) { sc[k] = -1.f; continue; }
            if (cl[k] != wc) continue;
            float4 b = bx[k];
            float iw = fmaxf(fminf(wb.z, b.z) - fmaxf(wb.x, b.x), 0.f);
            float ih = fmaxf(fminf(wb.w, b.w) - fmaxf(wb.y, b.y), 0.f);
            float inter = iw * ih;
            float iou = inter / (wa + ar[k] - inter + 1e-6f);
            if (iou > iouT) sc[k] = -1.f;
        }
        if (tid == 0) {
            oB[t*4+0] = wb.x; oB[t*4+1] = wb.y; oB[t*4+2] = wb.z; oB[t*4+3] = wb.w;
            oS[t] = wv;
            oC[t] = (float)wc;
        }
        __syncthreads();
    }
    for (int u = t + tid; u < imtop; u += NMS_T) {
        oB[u*4+0] = 0.f; oB[u*4+1] = 0.f; oB[u*4+2] = 0.f; oB[u*4+3] = 0.f;
        oS[u] = 0.f;
        oC[u] = -1.f;
    }
}

/* ------------------ host launch ---------------------------------------------------- */
extern "C" void kernel_launch(void* const* d_in, const int* in_sizes, int n_in,
                              void* d_out, int out_size)
{
    const float* prop    = (const float*)d_in[0];
    const int*   imidx   = (const int*)  d_in[1];
    const float* f0      = (const float*)d_in[2];
    const float* f1      = (const float*)d_in[3];
    const float* f2      = (const float*)d_in[4];
    const float* f3      = (const float*)d_in[5];
    const float* W0      = (const float*)d_in[6];
    const float* b0      = (const float*)d_in[7];
    const float* W1      = (const float*)d_in[8];
    const float* b1      = (const float*)d_in[9];
    const float* Wc      = (const float*)d_in[10];
    const float* bc      = (const float*)d_in[11];
    const float* Wr      = (const float*)d_in[12];
    const float* br      = (const float*)d_in[13];
    const float* imsizes = (const float*)d_in[14];
    const float* sthr    = (const float*)d_in[15];
    const float* iouthr  = (const float*)d_in[16];
    const float* minsz   = (const float*)d_in[18];

    int R  = in_sizes[0] / 4;
    int n  = in_sizes[14] / 2;
    int imtop = out_size / (6 * n);
    int N0 = in_sizes[7];
    int N1 = in_sizes[9];
    int NC = in_sizes[11];
    int NR = in_sizes[13];
    int NT = NC + NR;
    int D  = NC - 1;
    int M  = R * D;

    int H0 = (int)(sqrt((double)in_sizes[2] / ((double)n * C_CH)) + 0.5);
    int H1 = (int)(sqrt((double)in_sizes[3] / ((double)n * C_CH)) + 0.5);
    int H2 = (int)(sqrt((double)in_sizes[4] / ((double)n * C_CH)) + 0.5);
    int H3 = (int)(sqrt((double)in_sizes[5] / ((double)n * C_CH)) + 0.5);

    __half *px0h, *px0l, *pW0h, *pW0l, *pW1h, *pW1l, *pWhh, *pWhl;
    __half *px1h, *px1l, *px2h, *px2l;
    float *phead, *pbh, *ppart;
    cudaGetSymbolAddress((void**)&px0h, g_x0h);  cudaGetSymbolAddress((void**)&px0l, g_x0l);
    cudaGetSymbolAddress((void**)&pW0h, g_W0th); cudaGetSymbolAddress((void**)&pW0l, g_W0tl);
    cudaGetSymbolAddress((void**)&pW1h, g_W1th); cudaGetSymbolAddress((void**)&pW1l, g_W1tl);
    cudaGetSymbolAddress((void**)&pWhh, g_Whth); cudaGetSymbolAddress((void**)&pWhl, g_Whtl);
    cudaGetSymbolAddress((void**)&px1h, g_x1h);  cudaGetSymbolAddress((void**)&px1l, g_x1l);
    cudaGetSymbolAddress((void**)&px2h, g_x2h);  cudaGetSymbolAddress((void**)&px2l, g_x2l);
    cudaGetSymbolAddress((void**)&phead, g_headout);
    cudaGetSymbolAddress((void**)&pbh,   g_bhead);
    cudaGetSymbolAddress((void**)&ppart, g_part);

    cudaFuncSetAttribute(gemm_h2, cudaFuncAttributeMaxDynamicSharedMemorySize, GT_DSMEM);
    cudaFuncSetAttribute(nms_kernel, cudaFuncAttributeMaxDynamicSharedMemorySize, NMS_CAP*4);

    static cudaStream_t s2 = nullptr;
    static cudaEvent_t evFork = nullptr, evJoin = nullptr;
    if (!s2) {
        cudaStreamCreateWithFlags(&s2, cudaStreamNonBlocking);
        cudaEventCreateWithFlags(&evFork, cudaEventDisableTiming);
        cudaEventCreateWithFlags(&evJoin, cudaEventDisableTiming);
    }

    cudaEventRecord(evFork, 0);
    cudaStreamWaitEvent(s2, evFork, 0);

    /* 1. ROI align (stream 0) || weight prep + ccnt zero (stream s2) */
    roi_align_kernel<<<R, 256>>>(prop, imidx, f0, f1, f2, f3, H0, H1, H2, H3);
    {
        dim3 b(32, 8);
        tsplit_all_kernel<<<dim3(32, 488), b, 0, s2>>>(W0, W1, Wc, Wr, N0, N1, NC, NR);
        pack_bias_kernel<<<1, 512, 0, s2>>>(bc, br, NC, NR);
    }
    cudaEventRecord(evJoin, s2);
    cudaStreamWaitEvent(0, evJoin, 0);

    int rdT = 256;

    /* 2. FC1 (FEAT->N0): split-K x7 + reduce(relu+split) */
    {
        dim3 g((N0 + 63)/64, (R + 127)/128, 7);
        gemm_h2<<<g, 256, GT_DSMEM>>>(px0h, px0l, pW0h, pW0l, ppart, R, N0, FEAT, 1792);
        size_t tot = (size_t)R * N0;
        int thr = (int)((N0 & 3) == 0 ? (tot + 3)/4 : tot);
        reduce_kernel<<<(thr + rdT - 1)/rdT, rdT>>>(ppart, b0, R, N0, 7, 1,
                                                    nullptr, px1h, px1l);
    }
    /* 3. FC2 (N0->N1): split-K x2 + reduce(relu+split) */
    {
        dim3 g((N1 + 63)/64, (R + 127)/128, 2);
        gemm_h2<<<g, 256, GT_DSMEM>>>(px1h, px1l, pW1h, pW1l, ppart, R, N1, N0, 512);
        size_t tot = (size_t)R * N1;
        int thr = (int)((N1 & 3) == 0 ? (tot + 3)/4 : tot);
        reduce_kernel<<<(thr + rdT - 1)/rdT, rdT>>>(ppart, b1, R, N1, 2, 1,
                                                    nullptr, px2h, px2l);
    }
    /* 4. fused class+reg head (N1->NT): split-K x5 + reduce(fp32) */
    {
        dim3 g((NT + 63)/64, (R + 127)/128, 5);
        gemm_h2<<<g, 256, GT_DSMEM>>>(px2h, px2l, pWhh, pWhl, ppart, R, NT, N1, 224);
        size_t tot = (size_t)R * NT;
        int thr = (int)((NT & 3) == 0 ? (tot + 3)/4 : tot);
        reduce_kernel<<<(thr + rdT - 1)/rdT, rdT>>>(ppart, pbh, R, NT, 5, 0,
                                                    phead, nullptr, nullptr);
    }
    /* 5. softmax + decode + fused chunk counts */
    decode_kernel<<<R, 128>>>(prop, imidx, imsizes, sthr, minsz, NC, NT);

    /* 6. compaction scatter (prefix from fused counts) */
    {
        int nch = (M + CCH - 1) / CCH;
        compact_scatter_kernel<<<dim3(nch, n), 256>>>(imidx, M, D, nch);
    }

    /* 7. sequential NMS + output write */
    nms_kernel<<<n, NMS_T, NMS_CAP*4>>>(iouthr, (float*)d_out, n, imtop);
}